// round 1
// baseline (speedup 1.0000x reference)
#include <cuda_runtime.h>

// ---------------- problem constants ----------------
constexpr int B  = 8;
constexpr int T  = 1024;
constexpr int D  = 1024;
constexpr int H  = 16;
constexpr int DH = 64;
constexpr float INV_SCALE = 0.125f;   // 1/sqrt(DH)
constexpr float EPS = 1e-13f;

// ---------------- scratch (device globals: no allocation allowed) ----------------
__device__ float g_q[(size_t)B * H * T * DH];   // 32 MB
__device__ float g_k[(size_t)B * H * T * DH];   // 32 MB
__device__ float g_v[(size_t)B * H * T * DH];   // 32 MB
__device__ float g_ctx[(size_t)B * T * D];      // 32 MB, [B*T, D] row-major

// ============================================================================
// Tiled fp32 GEMM:  C[m,n] = sum_k A[m,k] * W[n,k] + bias[n]
//   A: [M,K] row-major, W: [N,K] row-major (both K-contiguous)
//   MODE 0: A = param, output scattered into g_q/g_k/g_v per-head layout
//   MODE 1: A = g_ctx, output = C (plain row-major [M,N])
// Block tile 128x128x16, 256 threads, 8x8 micro-tile per thread.
// ============================================================================
constexpr int BM = 128, BN = 128, BK = 16;

template <int MODE>
__global__ void __launch_bounds__(256, 2)
sgemm_kernel(const float* __restrict__ A, const float* __restrict__ W,
             const float* __restrict__ bias, float* __restrict__ C,
             int M, int N, int K)
{
    __shared__ __align__(16) float As[BK][BM + 4];
    __shared__ __align__(16) float Bs[BK][BN + 4];

    const float* Asrc = (MODE == 1) ? (const float*)g_ctx : A;

    const int tid = threadIdx.x;
    const int tx = tid & 15;          // 0..15 -> n micro
    const int ty = tid >> 4;          // 0..15 -> m micro
    const int m0 = blockIdx.y * BM;
    const int n0 = blockIdx.x * BN;

    const float* Ab = Asrc + (size_t)m0 * K;
    const float* Wb = W    + (size_t)n0 * K;

    const int lr = tid >> 2;          // 0..63 : tile row
    const int lc = (tid & 3) << 2;    // 0,4,8,12 : tile col (float)

    float acc[8][8];
#pragma unroll
    for (int i = 0; i < 8; i++)
#pragma unroll
        for (int j = 0; j < 8; j++) acc[i][j] = 0.f;

    for (int k0 = 0; k0 < K; k0 += BK) {
#pragma unroll
        for (int hh = 0; hh < 2; hh++) {
            const int row = lr + hh * 64;
            float4 va = *(const float4*)(Ab + (size_t)row * K + k0 + lc);
            As[lc + 0][row] = va.x; As[lc + 1][row] = va.y;
            As[lc + 2][row] = va.z; As[lc + 3][row] = va.w;
            float4 vb = *(const float4*)(Wb + (size_t)row * K + k0 + lc);
            Bs[lc + 0][row] = vb.x; Bs[lc + 1][row] = vb.y;
            Bs[lc + 2][row] = vb.z; Bs[lc + 3][row] = vb.w;
        }
        __syncthreads();

#pragma unroll
        for (int kk = 0; kk < BK; kk++) {
            float a[8], b[8];
            *(float4*)&a[0] = *(const float4*)&As[kk][ty * 8];
            *(float4*)&a[4] = *(const float4*)&As[kk][ty * 8 + 4];
            *(float4*)&b[0] = *(const float4*)&Bs[kk][tx * 8];
            *(float4*)&b[4] = *(const float4*)&Bs[kk][tx * 8 + 4];
#pragma unroll
            for (int i = 0; i < 8; i++)
#pragma unroll
                for (int j = 0; j < 8; j++)
                    acc[i][j] += a[i] * b[j];
        }
        __syncthreads();
    }

    if (MODE == 0) {
        // scatter into Q/K/V [B,H,T,DH].  n-tile of 128 never crosses the
        // 1024 boundary (128 | 1024), so sel is block-constant.
        const int sel = n0 >> 10;
        float* dst = (sel == 0) ? g_q : (sel == 1) ? g_k : g_v;
#pragma unroll
        for (int i = 0; i < 8; i++) {
            const int m  = m0 + ty * 8 + i;
            const int bb = m >> 10;
            const int t  = m & 1023;
#pragma unroll
            for (int jj = 0; jj < 2; jj++) {
                const int n  = n0 + tx * 8 + jj * 4;
                const int hh = (n & 1023) >> 6;
                const int d  = n & 63;
                float4 v;
                v.x = acc[i][jj * 4 + 0] + bias[n + 0];
                v.y = acc[i][jj * 4 + 1] + bias[n + 1];
                v.z = acc[i][jj * 4 + 2] + bias[n + 2];
                v.w = acc[i][jj * 4 + 3] + bias[n + 3];
                *(float4*)&dst[((size_t)(bb * H + hh) * T + t) * DH + d] = v;
            }
        }
    } else {
#pragma unroll
        for (int i = 0; i < 8; i++) {
            const int m = m0 + ty * 8 + i;
#pragma unroll
            for (int jj = 0; jj < 2; jj++) {
                const int n = n0 + tx * 8 + jj * 4;
                float4 v;
                v.x = acc[i][jj * 4 + 0] + bias[n + 0];
                v.y = acc[i][jj * 4 + 1] + bias[n + 1];
                v.z = acc[i][jj * 4 + 2] + bias[n + 2];
                v.w = acc[i][jj * 4 + 3] + bias[n + 3];
                *(float4*)&C[(size_t)m * N + n] = v;
            }
        }
    }
}

// ============================================================================
// Fused flash attention with adj scale + mask + renormalization.
//   per block: (b, h, 128 q-rows). Streams over k in tiles of 64.
//   out[r,:] = sum_c e^{sm-mx}*m_c*V[c,:] / (Sum e^{sm-mx}*m_c + EPS*Sum e^{sm-mx})
//   where sm = (q.k / SCALE) * adj * m_c   (exactly matches reference algebra).
// 256 threads: 16(ty: 8 q-rows each) x 16(tx: 4 cols each).
// ============================================================================
constexpr int QT = 128;               // q rows per block
constexpr int KT = 64;                // k cols per tile
constexpr int QS = 68;                // padded smem row stride (floats)
constexpr int ATTN_SMEM_BYTES = (QT * QS + KT * QS + KT * QS + QT * QS + KT) * 4;

__global__ void __launch_bounds__(256, 2)
attn_kernel(const float* __restrict__ adj, const float* __restrict__ mask)
{
    extern __shared__ __align__(16) float sh[];
    float* Qs  = sh;                          // [128][QS]  q (pre-scaled)
    float* KsT = Qs  + QT * QS;               // [64][QS]   K transposed: [d][c]
    float* Vs  = KsT + KT * QS;               // [64][QS]   V: [c][dv]
    float* PA  = Vs  + KT * QS;               // [128][QS]  adj tile, then P
    float* MS  = PA  + QT * QS;               // [64]       mask chunk

    const int b  = blockIdx.z;
    const int h  = blockIdx.y;
    const int q0 = blockIdx.x * QT;
    const int tid = threadIdx.x;
    const int tx = tid & 15;
    const int ty = tid >> 4;
    const int r0 = ty * 8;                    // this thread's first q-row
    const int c0 = tx * 4;                    // this thread's first col (k / dv)

    const float* qptr  = g_q + ((size_t)(b * H + h) * T + q0) * DH;
    const float* kbase = g_k + (size_t)(b * H + h) * T * DH;
    const float* vbase = g_v + (size_t)(b * H + h) * T * DH;

    // load Q tile, fold in 1/SCALE
    for (int idx = tid; idx < QT * 16; idx += 256) {
        const int r  = idx >> 4;
        const int c4 = (idx & 15) << 2;
        float4 v = *(const float4*)(qptr + (size_t)r * DH + c4);
        v.x *= INV_SCALE; v.y *= INV_SCALE; v.z *= INV_SCALE; v.w *= INV_SCALE;
        *(float4*)&Qs[r * QS + c4] = v;
    }

    float mx[8], l1[8], l2[8];
    float4 acc[8];
#pragma unroll
    for (int i = 0; i < 8; i++) {
        mx[i] = -1e30f; l1[i] = 0.f; l2[i] = 0.f;
        acc[i] = make_float4(0.f, 0.f, 0.f, 0.f);
    }

    for (int kt = 0; kt < T / KT; kt++) {
        const int kk0 = kt * KT;

        // ---- load K (transposed to [d][c]), V, adj tile, mask chunk ----
        for (int idx = tid; idx < KT * 16; idx += 256) {
            const int r  = idx >> 4;              // k row 0..63
            const int c4 = (idx & 15) << 2;       // d 0..60
            float4 kv = *(const float4*)(kbase + (size_t)(kk0 + r) * DH + c4);
            KsT[(c4 + 0) * QS + r] = kv.x;
            KsT[(c4 + 1) * QS + r] = kv.y;
            KsT[(c4 + 2) * QS + r] = kv.z;
            KsT[(c4 + 3) * QS + r] = kv.w;
            float4 vv = *(const float4*)(vbase + (size_t)(kk0 + r) * DH + c4);
            *(float4*)&Vs[r * QS + c4] = vv;
        }
        const float* aptr = adj + ((size_t)b * T + q0) * T + kk0;
        for (int idx = tid; idx < QT * 16; idx += 256) {
            const int r  = idx >> 4;
            const int c4 = (idx & 15) << 2;
            *(float4*)&PA[r * QS + c4] = *(const float4*)(aptr + (size_t)r * T + c4);
        }
        if (tid < KT) MS[tid] = mask[b * T + kk0 + tid];
        __syncthreads();

        // ---- S = Q @ K^T (each thread: 8 rows x 4 cols) ----
        float s[8][4];
#pragma unroll
        for (int i = 0; i < 8; i++)
#pragma unroll
            for (int j = 0; j < 4; j++) s[i][j] = 0.f;

#pragma unroll
        for (int d4 = 0; d4 < 16; d4++) {
            float4 kb[4];                        // kb[u] = K[d4*4+u][c0..c0+3]
#pragma unroll
            for (int u = 0; u < 4; u++)
                kb[u] = *(const float4*)&KsT[(d4 * 4 + u) * QS + c0];
#pragma unroll
            for (int i = 0; i < 8; i++) {
                float4 qv = *(const float4*)&Qs[(r0 + i) * QS + d4 * 4];
                s[i][0] += qv.x * kb[0].x + qv.y * kb[1].x + qv.z * kb[2].x + qv.w * kb[3].x;
                s[i][1] += qv.x * kb[0].y + qv.y * kb[1].y + qv.z * kb[2].y + qv.w * kb[3].y;
                s[i][2] += qv.x * kb[0].z + qv.y * kb[1].z + qv.z * kb[2].z + qv.w * kb[3].z;
                s[i][3] += qv.x * kb[0].w + qv.y * kb[1].w + qv.z * kb[2].w + qv.w * kb[3].w;
            }
        }

        // ---- adj * mask, online softmax update, write P into PA ----
        float mv[4];
#pragma unroll
        for (int j = 0; j < 4; j++) mv[j] = MS[c0 + j];

#pragma unroll
        for (int i = 0; i < 8; i++) {
            float sm[4];
            float rmax = -1e30f;
#pragma unroll
            for (int j = 0; j < 4; j++) {
                const float aa = PA[(r0 + i) * QS + c0 + j];
                sm[j] = s[i][j] * aa * mv[j];
                rmax = fmaxf(rmax, sm[j]);
            }
#pragma unroll
            for (int o = 8; o > 0; o >>= 1)
                rmax = fmaxf(rmax, __shfl_xor_sync(0xffffffffu, rmax, o, 16));

            const float mnew  = fmaxf(mx[i], rmax);
            const float alpha = __expf(mx[i] - mnew);
            mx[i] = mnew;
            l1[i] *= alpha; l2[i] *= alpha;
            acc[i].x *= alpha; acc[i].y *= alpha; acc[i].z *= alpha; acc[i].w *= alpha;

            float s1 = 0.f, s2 = 0.f;
#pragma unroll
            for (int j = 0; j < 4; j++) {
                const float p  = __expf(sm[j] - mnew);
                const float pm = p * mv[j];
                s2 += p; s1 += pm;
                PA[(r0 + i) * QS + c0 + j] = pm;   // own element: no race
            }
#pragma unroll
            for (int o = 8; o > 0; o >>= 1) {
                s1 += __shfl_xor_sync(0xffffffffu, s1, o, 16);
                s2 += __shfl_xor_sync(0xffffffffu, s2, o, 16);
            }
            l1[i] += s1; l2[i] += s2;
        }
        __syncthreads();

        // ---- acc += P @ V ----
#pragma unroll
        for (int c4 = 0; c4 < 16; c4++) {
            float4 vr[4];                        // vr[u] = V[c4*4+u][c0..c0+3]
#pragma unroll
            for (int u = 0; u < 4; u++)
                vr[u] = *(const float4*)&Vs[(c4 * 4 + u) * QS + c0];
#pragma unroll
            for (int i = 0; i < 8; i++) {
                float4 pv = *(const float4*)&PA[(r0 + i) * QS + c4 * 4];
                acc[i].x += pv.x * vr[0].x + pv.y * vr[1].x + pv.z * vr[2].x + pv.w * vr[3].x;
                acc[i].y += pv.x * vr[0].y + pv.y * vr[1].y + pv.z * vr[2].y + pv.w * vr[3].y;
                acc[i].z += pv.x * vr[0].z + pv.y * vr[1].z + pv.z * vr[2].z + pv.w * vr[3].z;
                acc[i].w += pv.x * vr[0].w + pv.y * vr[1].w + pv.z * vr[2].w + pv.w * vr[3].w;
            }
        }
        __syncthreads();
    }

    // ---- normalize and write ctx [B*T, D] with per-head column offset ----
#pragma unroll
    for (int i = 0; i < 8; i++) {
        const float inv = 1.0f / (l1[i] + EPS * l2[i]);
        float4 o = acc[i];
        o.x *= inv; o.y *= inv; o.z *= inv; o.w *= inv;
        const int row = q0 + r0 + i;
        *(float4*)&g_ctx[(size_t)(b * T + row) * D + h * DH + c0] = o;
    }
}

// ============================================================================
// launch
// ============================================================================
extern "C" void kernel_launch(void* const* d_in, const int* in_sizes, int n_in,
                              void* d_out, int out_size)
{
    (void)in_sizes; (void)n_in; (void)out_size;
    const float* inputs = (const float*)d_in[0];
    const float* mask   = (const float*)d_in[1];
    const float* adj    = (const float*)d_in[2];
    const float* W_qkv  = (const float*)d_in[3];
    const float* b_qkv  = (const float*)d_in[4];
    const float* W_out  = (const float*)d_in[5];
    const float* b_out  = (const float*)d_in[6];
    float* out = (float*)d_out;

    cudaFuncSetAttribute(attn_kernel,
                         cudaFuncAttributeMaxDynamicSharedMemorySize,
                         ATTN_SMEM_BYTES);

    dim3 blk(256);
    // QKV projection: M=8192, N=3072, K=1024
    sgemm_kernel<0><<<dim3((3 * D) / BN, (B * T) / BM), blk>>>(
        inputs, W_qkv, b_qkv, nullptr, B * T, 3 * D, D);

    // fused attention
    attn_kernel<<<dim3(T / QT, H, B), blk, ATTN_SMEM_BYTES>>>(adj, mask);

    // output projection: M=8192, N=1024, K=1024
    sgemm_kernel<1><<<dim3(D / BN, (B * T) / BM), blk>>>(
        nullptr, W_out, b_out, out, B * T, D, D);
}

// round 3
// speedup vs baseline: 1.7863x; 1.7863x over previous
#include <cuda_runtime.h>
#include <cstdint>

// ---------------- problem constants ----------------
constexpr int B  = 8;
constexpr int T  = 1024;
constexpr int D  = 1024;
constexpr int H  = 16;
constexpr int DH = 64;
constexpr float INV_SCALE = 0.125f;   // 1/sqrt(DH)
constexpr float EPS = 1e-13f;

// ---------------- scratch (device globals: no allocation allowed) ----------------
__device__ float g_q[(size_t)B * H * T * DH];   // 32 MB
__device__ float g_k[(size_t)B * H * T * DH];   // 32 MB
__device__ float g_v[(size_t)B * H * T * DH];   // 32 MB
__device__ float g_ctx[(size_t)B * T * D];      // 32 MB, [B*T, D] row-major

// ---------------- PTX helpers (base-arch only: no 'a'-suffix features) -------
__device__ __forceinline__ uint32_t smem_u32(const void* p) {
    uint32_t a;
    asm("{ .reg .u64 t; cvta.to.shared.u64 t, %1; cvt.u32.u64 %0, t; }"
        : "=r"(a) : "l"(p));
    return a;
}

#define CP_ASYNC16(dst, src) \
    asm volatile("cp.async.cg.shared.global [%0], [%1], 16;" :: "r"(dst), "l"(src))
#define CP_COMMIT()  asm volatile("cp.async.commit_group;" ::: "memory")
#define CP_WAIT(n)   asm volatile("cp.async.wait_group %0;" :: "n"(n) : "memory")

#define LDMATRIX_X4(r0, r1, r2, r3, addr) \
    asm volatile("ldmatrix.sync.aligned.m8n8.x4.shared.b16 {%0,%1,%2,%3}, [%4];" \
        : "=r"(r0), "=r"(r1), "=r"(r2), "=r"(r3) : "r"(addr))

__device__ __forceinline__ uint32_t f2tf32(uint32_t x) {
    uint32_t d;
    asm("cvt.rna.tf32.f32 %0, %1;" : "=r"(d) : "r"(x));
    return d;
}

__device__ __forceinline__ void mma_tf32(float* c, const uint32_t* a,
                                         uint32_t b0, uint32_t b1) {
    asm volatile(
        "mma.sync.aligned.m16n8k8.row.col.f32.tf32.tf32.f32 "
        "{%0,%1,%2,%3}, {%4,%5,%6,%7}, {%8,%9}, {%0,%1,%2,%3};"
        : "+f"(c[0]), "+f"(c[1]), "+f"(c[2]), "+f"(c[3])
        : "r"(a[0]), "r"(a[1]), "r"(a[2]), "r"(a[3]), "r"(b0), "r"(b1));
}

// ============================================================================
// tf32 mma.sync GEMM:  C[m,n] = sum_k A[m,k] * W[n,k] + bias[n]
//   A: [M,K] row-major, W: [N,K] row-major (mma row.col wants exactly this).
//   Tile 128x128x32, 256 threads = 8 warps (2 m x 4 n), 64x32 per warp.
//   MODE 0: A = param, scatter into g_q/g_k/g_v;  MODE 1: A = g_ctx, row-major C.
// SMEM: per buffer A[128 rows][32 floats=128B] + B same, swizzled; double-buffered.
// ============================================================================
constexpr int GBK = 32;                         // K per chunk
constexpr int G_TILE = 128 * 128;               // 16 KB (128 rows x 128B)
constexpr int GEMM_SMEM_BYTES = 4 * G_TILE;     // A0,B0,A1,B1 = 64 KB

__device__ __forceinline__ void load_chunk(uint32_t sA, uint32_t sB,
                                           const float* __restrict__ Ab,
                                           const float* __restrict__ Wb,
                                           int K, int k0) {
    const int tid = threadIdx.x;
#pragma unroll
    for (int it = 0; it < 4; it++) {
        const int idx = it * 256 + tid;          // 0..1023
        const int r = idx >> 3;
        const int s = idx & 7;
        const uint32_t off = (uint32_t)r * 128u + (((uint32_t)s * 16u) ^ (((uint32_t)r & 7u) << 4));
        CP_ASYNC16(sA + off, Ab + (size_t)r * K + k0 + s * 4);
    }
#pragma unroll
    for (int it = 0; it < 4; it++) {
        const int idx = it * 256 + tid;
        const int r = idx >> 3;
        const int s = idx & 7;
        const uint32_t off = (uint32_t)r * 128u + (((uint32_t)s * 16u) ^ (((uint32_t)r & 7u) << 4));
        CP_ASYNC16(sB + off, Wb + (size_t)r * K + k0 + s * 4);
    }
}

template <int MODE>
__global__ void __launch_bounds__(256)
gemm_mma_kernel(const float* __restrict__ A, const float* __restrict__ W,
                const float* __restrict__ bias, float* __restrict__ C,
                int K, int Ntot)
{
    extern __shared__ __align__(1024) char smem[];
    const uint32_t sbase = smem_u32(smem);
    const int tid  = threadIdx.x;
    const int wid  = tid >> 5;
    const int lane = tid & 31;

    const int m0 = blockIdx.y * 128;
    const int n0 = blockIdx.x * 128;

    const float* Asrc = (MODE == 1) ? (const float*)g_ctx : A;
    const float* Ab = Asrc + (size_t)m0 * K;
    const float* Wb = W    + (size_t)n0 * K;

    const uint32_t sA[2] = { sbase,              sbase + 2 * G_TILE };
    const uint32_t sB[2] = { sbase + G_TILE,     sbase + 3 * G_TILE };

    // warp tile: 64 m x 32 n
    const int wm = (wid >> 2) * 64;
    const int wn = (wid & 3) * 32;

    // ldmatrix per-lane addressing (within a buffer; add buffer base later)
    // A fragment (m16k8): lanes 0-7 rows0-7 klo | 8-15 rows8-15 klo | 16-23 rows0-7 khi | 24-31 rows8-15 khi
    const int arow   = wm + (lane & 15);
    const uint32_t aoff  = (uint32_t)arow * 128u;
    const uint32_t aswz  = ((uint32_t)arow & 7u) << 4;
    const uint32_t akhi  = (uint32_t)(lane & 16);          // 0 or 16 bytes
    // B fragments (two n-tiles per x4): lanes 0-7 n0-7 klo | 8-15 n0-7 khi | 16-23 n8-15 klo | 24-31 n8-15 khi
    const int brow   = wn + (lane & 7) + ((lane & 16) >> 1);
    const uint32_t boff  = (uint32_t)brow * 128u;
    const uint32_t bswz  = ((uint32_t)brow & 7u) << 4;
    const uint32_t bkhi  = (uint32_t)((lane & 8) << 1);    // 0 or 16 bytes

    float acc[4][4][4];
#pragma unroll
    for (int i = 0; i < 4; i++)
#pragma unroll
        for (int j = 0; j < 4; j++)
#pragma unroll
            for (int e = 0; e < 4; e++) acc[i][j][e] = 0.f;

    const int NC = K / GBK;

    // prologue
    load_chunk(sA[0], sB[0], Ab, Wb, K, 0);
    CP_COMMIT();

    for (int i = 0; i < NC; i++) {
        const int bsel = i & 1;

        if (i + 1 < NC) {
            load_chunk(sA[1 - bsel], sB[1 - bsel], Ab, Wb, K, (i + 1) * GBK);
            CP_COMMIT();
            CP_WAIT(1);
        } else {
            CP_WAIT(0);
        }
        __syncthreads();

        const uint32_t aB = sA[bsel];
        const uint32_t bB = sB[bsel];

#pragma unroll
        for (int ks = 0; ks < 4; ks++) {
            const uint32_t kb = (uint32_t)ks * 32u;

            uint32_t afr[4][4];
#pragma unroll
            for (int tm = 0; tm < 4; tm++) {
                const uint32_t addr = aB + aoff + (uint32_t)tm * 2048u + ((kb + akhi) ^ aswz);
                LDMATRIX_X4(afr[tm][0], afr[tm][1], afr[tm][2], afr[tm][3], addr);
            }
            uint32_t bfr[2][4];
#pragma unroll
            for (int tp = 0; tp < 2; tp++) {
                const uint32_t addr = bB + boff + (uint32_t)tp * 2048u + ((kb + bkhi) ^ bswz);
                LDMATRIX_X4(bfr[tp][0], bfr[tp][1], bfr[tp][2], bfr[tp][3], addr);
            }
            // round to tf32 (HW truncates otherwise -> coherent bias)
#pragma unroll
            for (int tm = 0; tm < 4; tm++)
#pragma unroll
                for (int e = 0; e < 4; e++) afr[tm][e] = f2tf32(afr[tm][e]);
#pragma unroll
            for (int tp = 0; tp < 2; tp++)
#pragma unroll
                for (int e = 0; e < 4; e++) bfr[tp][e] = f2tf32(bfr[tp][e]);

#pragma unroll
            for (int tm = 0; tm < 4; tm++)
#pragma unroll
                for (int tn = 0; tn < 4; tn++)
                    mma_tf32(acc[tm][tn], afr[tm],
                             bfr[tn >> 1][(tn & 1) * 2 + 0],
                             bfr[tn >> 1][(tn & 1) * 2 + 1]);
        }
        __syncthreads();
    }

    // ---- epilogue: c regs -> global.  tile (tm,tn):
    //   rows: m0+wm+tm*16 + lane>>2 (+8), cols: n0+wn+tn*8 + 2*(lane&3) (+1)
#pragma unroll
    for (int tm = 0; tm < 4; tm++) {
#pragma unroll
        for (int tn = 0; tn < 4; tn++) {
            const int col = n0 + wn + tn * 8 + (lane & 3) * 2;
            const float bx = bias[col], by = bias[col + 1];
#pragma unroll
            for (int half = 0; half < 2; half++) {
                const int row = m0 + wm + tm * 16 + (lane >> 2) + half * 8;
                float2 v;
                v.x = acc[tm][tn][half * 2 + 0] + bx;
                v.y = acc[tm][tn][half * 2 + 1] + by;
                if (MODE == 0) {
                    const int sel = col >> 10;          // 128 | 1024: block-constant
                    float* dst = (sel == 0) ? g_q : (sel == 1) ? g_k : g_v;
                    const int bb = row >> 10;
                    const int t  = row & 1023;
                    const int hh = (col & 1023) >> 6;
                    const int d  = col & 63;
                    *(float2*)&dst[((size_t)(bb * H + hh) * T + t) * DH + d] = v;
                } else {
                    *(float2*)&C[(size_t)row * Ntot + col] = v;
                }
            }
        }
    }
}

// ============================================================================
// Fused flash attention with adj scale + mask + renormalization (unchanged).
// ============================================================================
constexpr int QT = 128;               // q rows per block
constexpr int KT = 64;                // k cols per tile
constexpr int QS = 68;                // padded smem row stride (floats)
constexpr int ATTN_SMEM_BYTES = (QT * QS + KT * QS + KT * QS + QT * QS + KT) * 4;

__global__ void __launch_bounds__(256, 2)
attn_kernel(const float* __restrict__ adj, const float* __restrict__ mask)
{
    extern __shared__ __align__(16) float sh[];
    float* Qs  = sh;                          // [128][QS]  q (pre-scaled)
    float* KsT = Qs  + QT * QS;               // [64][QS]   K transposed: [d][c]
    float* Vs  = KsT + KT * QS;               // [64][QS]   V: [c][dv]
    float* PA  = Vs  + KT * QS;               // [128][QS]  adj tile, then P
    float* MS  = PA  + QT * QS;               // [64]       mask chunk

    const int b  = blockIdx.z;
    const int h  = blockIdx.y;
    const int q0 = blockIdx.x * QT;
    const int tid = threadIdx.x;
    const int tx = tid & 15;
    const int ty = tid >> 4;
    const int r0 = ty * 8;                    // this thread's first q-row
    const int c0 = tx * 4;                    // this thread's first col (k / dv)

    const float* qptr  = g_q + ((size_t)(b * H + h) * T + q0) * DH;
    const float* kbase = g_k + (size_t)(b * H + h) * T * DH;
    const float* vbase = g_v + (size_t)(b * H + h) * T * DH;

    // load Q tile, fold in 1/SCALE
    for (int idx = tid; idx < QT * 16; idx += 256) {
        const int r  = idx >> 4;
        const int c4 = (idx & 15) << 2;
        float4 v = *(const float4*)(qptr + (size_t)r * DH + c4);
        v.x *= INV_SCALE; v.y *= INV_SCALE; v.z *= INV_SCALE; v.w *= INV_SCALE;
        *(float4*)&Qs[r * QS + c4] = v;
    }

    float mx[8], l1[8], l2[8];
    float4 acc[8];
#pragma unroll
    for (int i = 0; i < 8; i++) {
        mx[i] = -1e30f; l1[i] = 0.f; l2[i] = 0.f;
        acc[i] = make_float4(0.f, 0.f, 0.f, 0.f);
    }

    for (int kt = 0; kt < T / KT; kt++) {
        const int kk0 = kt * KT;

        // ---- load K (transposed to [d][c]), V, adj tile, mask chunk ----
        for (int idx = tid; idx < KT * 16; idx += 256) {
            const int r  = idx >> 4;              // k row 0..63
            const int c4 = (idx & 15) << 2;       // d 0..60
            float4 kv = *(const float4*)(kbase + (size_t)(kk0 + r) * DH + c4);
            KsT[(c4 + 0) * QS + r] = kv.x;
            KsT[(c4 + 1) * QS + r] = kv.y;
            KsT[(c4 + 2) * QS + r] = kv.z;
            KsT[(c4 + 3) * QS + r] = kv.w;
            float4 vv = *(const float4*)(vbase + (size_t)(kk0 + r) * DH + c4);
            *(float4*)&Vs[r * QS + c4] = vv;
        }
        const float* aptr = adj + ((size_t)b * T + q0) * T + kk0;
        for (int idx = tid; idx < QT * 16; idx += 256) {
            const int r  = idx >> 4;
            const int c4 = (idx & 15) << 2;
            *(float4*)&PA[r * QS + c4] = *(const float4*)(aptr + (size_t)r * T + c4);
        }
        if (tid < KT) MS[tid] = mask[b * T + kk0 + tid];
        __syncthreads();

        // ---- S = Q @ K^T (each thread: 8 rows x 4 cols) ----
        float s[8][4];
#pragma unroll
        for (int i = 0; i < 8; i++)
#pragma unroll
            for (int j = 0; j < 4; j++) s[i][j] = 0.f;

#pragma unroll
        for (int d4 = 0; d4 < 16; d4++) {
            float4 kb[4];                        // kb[u] = K[d4*4+u][c0..c0+3]
#pragma unroll
            for (int u = 0; u < 4; u++)
                kb[u] = *(const float4*)&KsT[(d4 * 4 + u) * QS + c0];
#pragma unroll
            for (int i = 0; i < 8; i++) {
                float4 qv = *(const float4*)&Qs[(r0 + i) * QS + d4 * 4];
                s[i][0] += qv.x * kb[0].x + qv.y * kb[1].x + qv.z * kb[2].x + qv.w * kb[3].x;
                s[i][1] += qv.x * kb[0].y + qv.y * kb[1].y + qv.z * kb[2].y + qv.w * kb[3].y;
                s[i][2] += qv.x * kb[0].z + qv.y * kb[1].z + qv.z * kb[2].z + qv.w * kb[3].z;
                s[i][3] += qv.x * kb[0].w + qv.y * kb[1].w + qv.z * kb[2].w + qv.w * kb[3].w;
            }
        }

        // ---- adj * mask, online softmax update, write P into PA ----
        float mv[4];
#pragma unroll
        for (int j = 0; j < 4; j++) mv[j] = MS[c0 + j];

#pragma unroll
        for (int i = 0; i < 8; i++) {
            float sm[4];
            float rmax = -1e30f;
#pragma unroll
            for (int j = 0; j < 4; j++) {
                const float aa = PA[(r0 + i) * QS + c0 + j];
                sm[j] = s[i][j] * aa * mv[j];
                rmax = fmaxf(rmax, sm[j]);
            }
#pragma unroll
            for (int o = 8; o > 0; o >>= 1)
                rmax = fmaxf(rmax, __shfl_xor_sync(0xffffffffu, rmax, o, 16));

            const float mnew  = fmaxf(mx[i], rmax);
            const float alpha = __expf(mx[i] - mnew);
            mx[i] = mnew;
            l1[i] *= alpha; l2[i] *= alpha;
            acc[i].x *= alpha; acc[i].y *= alpha; acc[i].z *= alpha; acc[i].w *= alpha;

            float s1 = 0.f, s2 = 0.f;
#pragma unroll
            for (int j = 0; j < 4; j++) {
                const float p  = __expf(sm[j] - mnew);
                const float pm = p * mv[j];
                s2 += p; s1 += pm;
                PA[(r0 + i) * QS + c0 + j] = pm;   // own element: no race
            }
#pragma unroll
            for (int o = 8; o > 0; o >>= 1) {
                s1 += __shfl_xor_sync(0xffffffffu, s1, o, 16);
                s2 += __shfl_xor_sync(0xffffffffu, s2, o, 16);
            }
            l1[i] += s1; l2[i] += s2;
        }
        __syncthreads();

        // ---- acc += P @ V ----
#pragma unroll
        for (int c4 = 0; c4 < 16; c4++) {
            float4 vr[4];                        // vr[u] = V[c4*4+u][c0..c0+3]
#pragma unroll
            for (int u = 0; u < 4; u++)
                vr[u] = *(const float4*)&Vs[(c4 * 4 + u) * QS + c0];
#pragma unroll
            for (int i = 0; i < 8; i++) {
                float4 pv = *(const float4*)&PA[(r0 + i) * QS + c4 * 4];
                acc[i].x += pv.x * vr[0].x + pv.y * vr[1].x + pv.z * vr[2].x + pv.w * vr[3].x;
                acc[i].y += pv.x * vr[0].y + pv.y * vr[1].y + pv.z * vr[2].y + pv.w * vr[3].y;
                acc[i].z += pv.x * vr[0].z + pv.y * vr[1].z + pv.z * vr[2].z + pv.w * vr[3].z;
                acc[i].w += pv.x * vr[0].w + pv.y * vr[1].w + pv.z * vr[2].w + pv.w * vr[3].w;
            }
        }
        __syncthreads();
    }

    // ---- normalize and write ctx [B*T, D] with per-head column offset ----
#pragma unroll
    for (int i = 0; i < 8; i++) {
        const float inv = 1.0f / (l1[i] + EPS * l2[i]);
        float4 o = acc[i];
        o.x *= inv; o.y *= inv; o.z *= inv; o.w *= inv;
        const int row = q0 + r0 + i;
        *(float4*)&g_ctx[(size_t)(b * T + row) * D + h * DH + c0] = o;
    }
}

// ============================================================================
// launch
// ============================================================================
extern "C" void kernel_launch(void* const* d_in, const int* in_sizes, int n_in,
                              void* d_out, int out_size)
{
    (void)in_sizes; (void)n_in; (void)out_size;
    const float* inputs = (const float*)d_in[0];
    const float* mask   = (const float*)d_in[1];
    const float* adj    = (const float*)d_in[2];
    const float* W_qkv  = (const float*)d_in[3];
    const float* b_qkv  = (const float*)d_in[4];
    const float* W_out  = (const float*)d_in[5];
    const float* b_out  = (const float*)d_in[6];
    float* out = (float*)d_out;

    cudaFuncSetAttribute(gemm_mma_kernel<0>,
                         cudaFuncAttributeMaxDynamicSharedMemorySize,
                         GEMM_SMEM_BYTES);
    cudaFuncSetAttribute(gemm_mma_kernel<1>,
                         cudaFuncAttributeMaxDynamicSharedMemorySize,
                         GEMM_SMEM_BYTES);
    cudaFuncSetAttribute(attn_kernel,
                         cudaFuncAttributeMaxDynamicSharedMemorySize,
                         ATTN_SMEM_BYTES);

    dim3 blk(256);
    // QKV projection: M=8192, N=3072, K=1024  (tf32 mma.sync)
    gemm_mma_kernel<0><<<dim3((3 * D) / 128, (B * T) / 128), blk, GEMM_SMEM_BYTES>>>(
        inputs, W_qkv, b_qkv, nullptr, D, 3 * D);

    // fused attention (fp32 SIMT)
    attn_kernel<<<dim3(T / QT, H, B), blk, ATTN_SMEM_BYTES>>>(adj, mask);

    // output projection: M=8192, N=1024, K=1024  (tf32 mma.sync)
    gemm_mma_kernel<1><<<dim3(D / 128, (B * T) / 128), blk, GEMM_SMEM_BYTES>>>(
        nullptr, W_out, b_out, out, D, D);
}

// round 4
// speedup vs baseline: 2.8955x; 1.6210x over previous
#include <cuda_runtime.h>
#include <cstdint>

// ---------------- problem constants ----------------
constexpr int B  = 8;
constexpr int T  = 1024;
constexpr int D  = 1024;
constexpr int H  = 16;
constexpr int DH = 64;
constexpr float INV_SCALE = 0.125f;   // 1/sqrt(DH)
constexpr float EPS = 1e-13f;

// ---------------- scratch (device globals: no allocation allowed) ----------------
__device__ float g_q[(size_t)B * H * T * DH];   // 32 MB
__device__ float g_k[(size_t)B * H * T * DH];   // 32 MB
__device__ float g_v[(size_t)B * H * T * DH];   // 32 MB
__device__ float g_ctx[(size_t)B * T * D];      // 32 MB, [B*T, D] row-major

// ---------------- PTX helpers (base-arch only) ----------------
__device__ __forceinline__ uint32_t smem_u32(const void* p) {
    uint32_t a;
    asm("{ .reg .u64 t; cvta.to.shared.u64 t, %1; cvt.u32.u64 %0, t; }"
        : "=r"(a) : "l"(p));
    return a;
}

#define CP_ASYNC16(dst, src) \
    asm volatile("cp.async.cg.shared.global [%0], [%1], 16;" :: "r"(dst), "l"(src))
#define CP_COMMIT()  asm volatile("cp.async.commit_group;" ::: "memory")
#define CP_WAIT(n)   asm volatile("cp.async.wait_group %0;" :: "n"(n) : "memory")

#define LDMATRIX_X4(r0, r1, r2, r3, addr) \
    asm volatile("ldmatrix.sync.aligned.m8n8.x4.shared.b16 {%0,%1,%2,%3}, [%4];" \
        : "=r"(r0), "=r"(r1), "=r"(r2), "=r"(r3) : "r"(addr))

__device__ __forceinline__ uint32_t f2tf32(uint32_t x) {
    uint32_t d;
    asm("cvt.rna.tf32.f32 %0, %1;" : "=r"(d) : "r"(x));
    return d;
}
__device__ __forceinline__ float tf32r(float x) {
    return __uint_as_float(f2tf32(__float_as_uint(x)));
}

__device__ __forceinline__ void mma_tf32(float* c, const uint32_t* a,
                                         uint32_t b0, uint32_t b1) {
    asm volatile(
        "mma.sync.aligned.m16n8k8.row.col.f32.tf32.tf32.f32 "
        "{%0,%1,%2,%3}, {%4,%5,%6,%7}, {%8,%9}, {%0,%1,%2,%3};"
        : "+f"(c[0]), "+f"(c[1]), "+f"(c[2]), "+f"(c[3])
        : "r"(a[0]), "r"(a[1]), "r"(a[2]), "r"(a[3]), "r"(b0), "r"(b1));
}

// ============================================================================
// tf32 mma.sync GEMM (unchanged from R3 — verified):
//   C[m,n] = sum_k A[m,k] * W[n,k] + bias[n]
// ============================================================================
constexpr int GBK = 32;
constexpr int G_TILE = 128 * 128;               // 16 KB
constexpr int GEMM_SMEM_BYTES = 4 * G_TILE;     // 64 KB

__device__ __forceinline__ void load_chunk(uint32_t sA, uint32_t sB,
                                           const float* __restrict__ Ab,
                                           const float* __restrict__ Wb,
                                           int K, int k0) {
    const int tid = threadIdx.x;
#pragma unroll
    for (int it = 0; it < 4; it++) {
        const int idx = it * 256 + tid;
        const int r = idx >> 3;
        const int s = idx & 7;
        const uint32_t off = (uint32_t)r * 128u + (((uint32_t)s * 16u) ^ (((uint32_t)r & 7u) << 4));
        CP_ASYNC16(sA + off, Ab + (size_t)r * K + k0 + s * 4);
    }
#pragma unroll
    for (int it = 0; it < 4; it++) {
        const int idx = it * 256 + tid;
        const int r = idx >> 3;
        const int s = idx & 7;
        const uint32_t off = (uint32_t)r * 128u + (((uint32_t)s * 16u) ^ (((uint32_t)r & 7u) << 4));
        CP_ASYNC16(sB + off, Wb + (size_t)r * K + k0 + s * 4);
    }
}

template <int MODE>
__global__ void __launch_bounds__(256)
gemm_mma_kernel(const float* __restrict__ A, const float* __restrict__ W,
                const float* __restrict__ bias, float* __restrict__ C,
                int K, int Ntot)
{
    extern __shared__ __align__(1024) char smem[];
    const uint32_t sbase = smem_u32(smem);
    const int tid  = threadIdx.x;
    const int wid  = tid >> 5;
    const int lane = tid & 31;

    const int m0 = blockIdx.y * 128;
    const int n0 = blockIdx.x * 128;

    const float* Asrc = (MODE == 1) ? (const float*)g_ctx : A;
    const float* Ab = Asrc + (size_t)m0 * K;
    const float* Wb = W    + (size_t)n0 * K;

    const uint32_t sA[2] = { sbase,          sbase + 2 * G_TILE };
    const uint32_t sB[2] = { sbase + G_TILE, sbase + 3 * G_TILE };

    const int wm = (wid >> 2) * 64;
    const int wn = (wid & 3) * 32;

    const int arow       = wm + (lane & 15);
    const uint32_t aoff  = (uint32_t)arow * 128u;
    const uint32_t aswz  = ((uint32_t)arow & 7u) << 4;
    const uint32_t akhi  = (uint32_t)(lane & 16);
    const int brow       = wn + (lane & 7) + ((lane & 16) >> 1);
    const uint32_t boff  = (uint32_t)brow * 128u;
    const uint32_t bswz  = ((uint32_t)brow & 7u) << 4;
    const uint32_t bkhi  = (uint32_t)((lane & 8) << 1);

    float acc[4][4][4];
#pragma unroll
    for (int i = 0; i < 4; i++)
#pragma unroll
        for (int j = 0; j < 4; j++)
#pragma unroll
            for (int e = 0; e < 4; e++) acc[i][j][e] = 0.f;

    const int NC = K / GBK;
    load_chunk(sA[0], sB[0], Ab, Wb, K, 0);
    CP_COMMIT();

    for (int i = 0; i < NC; i++) {
        const int bsel = i & 1;
        if (i + 1 < NC) {
            load_chunk(sA[1 - bsel], sB[1 - bsel], Ab, Wb, K, (i + 1) * GBK);
            CP_COMMIT();
            CP_WAIT(1);
        } else {
            CP_WAIT(0);
        }
        __syncthreads();

        const uint32_t aB = sA[bsel];
        const uint32_t bB = sB[bsel];

#pragma unroll
        for (int ks = 0; ks < 4; ks++) {
            const uint32_t kb = (uint32_t)ks * 32u;
            uint32_t afr[4][4];
#pragma unroll
            for (int tm = 0; tm < 4; tm++) {
                const uint32_t addr = aB + aoff + (uint32_t)tm * 2048u + ((kb + akhi) ^ aswz);
                LDMATRIX_X4(afr[tm][0], afr[tm][1], afr[tm][2], afr[tm][3], addr);
            }
            uint32_t bfr[2][4];
#pragma unroll
            for (int tp = 0; tp < 2; tp++) {
                const uint32_t addr = bB + boff + (uint32_t)tp * 2048u + ((kb + bkhi) ^ bswz);
                LDMATRIX_X4(bfr[tp][0], bfr[tp][1], bfr[tp][2], bfr[tp][3], addr);
            }
#pragma unroll
            for (int tm = 0; tm < 4; tm++)
#pragma unroll
                for (int e = 0; e < 4; e++) afr[tm][e] = f2tf32(afr[tm][e]);
#pragma unroll
            for (int tp = 0; tp < 2; tp++)
#pragma unroll
                for (int e = 0; e < 4; e++) bfr[tp][e] = f2tf32(bfr[tp][e]);

#pragma unroll
            for (int tm = 0; tm < 4; tm++)
#pragma unroll
                for (int tn = 0; tn < 4; tn++)
                    mma_tf32(acc[tm][tn], afr[tm],
                             bfr[tn >> 1][(tn & 1) * 2 + 0],
                             bfr[tn >> 1][(tn & 1) * 2 + 1]);
        }
        __syncthreads();
    }

#pragma unroll
    for (int tm = 0; tm < 4; tm++) {
#pragma unroll
        for (int tn = 0; tn < 4; tn++) {
            const int col = n0 + wn + tn * 8 + (lane & 3) * 2;
            const float bx = bias[col], by = bias[col + 1];
#pragma unroll
            for (int half = 0; half < 2; half++) {
                const int row = m0 + wm + tm * 16 + (lane >> 2) + half * 8;
                float2 v;
                v.x = acc[tm][tn][half * 2 + 0] + bx;
                v.y = acc[tm][tn][half * 2 + 1] + by;
                if (MODE == 0) {
                    const int sel = col >> 10;
                    float* dst = (sel == 0) ? g_q : (sel == 1) ? g_k : g_v;
                    const int bb = row >> 10;
                    const int t  = row & 1023;
                    const int hh = (col & 1023) >> 6;
                    const int d  = col & 63;
                    *(float2*)&dst[((size_t)(bb * H + hh) * T + t) * DH + d] = v;
                } else {
                    *(float2*)&C[(size_t)row * Ntot + col] = v;
                }
            }
        }
    }
}

// ============================================================================
// Fused flash attention on tensor cores (tf32 mma.sync).
//   Block: (b, h, 128 q-rows). 8 warps, warp owns 16 q-rows (full 64-col span
//   -> row reductions stay inside a 4-lane group). k-tiles of 64.
// SMEM rows padded to 68 floats (272B): ldmatrix conflict-free w/o XOR.
// VT uses a d-dependent 16B-chunk XOR so the transpose STS.32 is conflict-free.
// ============================================================================
constexpr int AQT = 128;
constexpr int AKT = 64;
constexpr int ASS = 68;                              // row stride in floats
constexpr int ATTN_SMEM_BYTES =
    (AQT * ASS + AKT * ASS + AKT * ASS + AQT * ASS + AKT) * 4;  // 104,704 B

__global__ void __launch_bounds__(256, 2)
attn_mma_kernel(const float* __restrict__ adj, const float* __restrict__ mask)
{
    extern __shared__ __align__(16) float sh[];
    float* Qs = sh;                    // [128][68] Q, tf32, pre-scaled
    float* Ks = Qs + AQT * ASS;        // [64][68]  K rows=c cols=d, tf32
    float* VT = Ks + AKT * ASS;        // [64][68]  rows=d cols=c (chunk-XOR), tf32
    float* Ps = VT + AKT * ASS;        // [128][68] adj tile, then P (tf32)
    float* MS = Ps + AQT * ASS;        // [64]

    const int b   = blockIdx.z;
    const int h   = blockIdx.y;
    const int q0g = blockIdx.x * AQT;
    const int tid = threadIdx.x;
    const int wid = tid >> 5;
    const int lane = tid & 31;
    const int q0  = wid * 16;                        // warp's q-row base (block-local)

    const float* qptr  = g_q + ((size_t)(b * H + h) * T + q0g) * DH;
    const float* kbase = g_k + (size_t)(b * H + h) * T * DH;
    const float* vbase = g_v + (size_t)(b * H + h) * T * DH;

    const uint32_t sQ = smem_u32(Qs);
    const uint32_t sK = smem_u32(Ks);
    const uint32_t sV = smem_u32(VT);
    const uint32_t sP = smem_u32(Ps);

    // ---- load Q once: scale + tf32-round ----
#pragma unroll
    for (int it = 0; it < 8; it++) {
        const int idx = it * 256 + tid;
        const int r = idx >> 4, s = idx & 15;
        float4 v = *(const float4*)(qptr + (size_t)r * DH + s * 4);
        v.x = tf32r(v.x * INV_SCALE); v.y = tf32r(v.y * INV_SCALE);
        v.z = tf32r(v.z * INV_SCALE); v.w = tf32r(v.w * INV_SCALE);
        *(float4*)&Qs[r * ASS + s * 4] = v;
    }

    // fragment lane addressing (byte offsets; verified mapping from GEMM)
    const uint32_t a_row_off = (uint32_t)(q0 + (lane & 15)) * 272u;
    const uint32_t a_khi     = (uint32_t)(lane & 16);
    const int      b_rl      = (lane & 7) + ((lane & 16) >> 1);
    const uint32_t b_khi     = (uint32_t)((lane & 8) << 1);

    float oacc[8][4];
#pragma unroll
    for (int tn = 0; tn < 8; tn++)
#pragma unroll
        for (int e = 0; e < 4; e++) oacc[tn][e] = 0.f;
    float mx[2] = { -1e30f, -1e30f };
    float l1[2] = { 0.f, 0.f };
    float l2[2] = { 0.f, 0.f };

    for (int kt = 0; kt < T / AKT; kt++) {
        const int kk0 = kt * AKT;
        __syncthreads();   // previous tile fully consumed

        // ---- K tile: LDG.128 -> tf32 -> STS.128 ----
#pragma unroll
        for (int it = 0; it < 4; it++) {
            const int idx = it * 256 + tid;
            const int r = idx >> 4, s = idx & 15;
            float4 v = *(const float4*)(kbase + (size_t)(kk0 + r) * DH + s * 4);
            v.x = tf32r(v.x); v.y = tf32r(v.y); v.z = tf32r(v.z); v.w = tf32r(v.w);
            *(float4*)&Ks[r * ASS + s * 4] = v;
        }
        // ---- V tile transposed: coalesced LDG.32, conflict-free STS.32 ----
#pragma unroll
        for (int it = 0; it < 16; it++) {
            const int idx = it * 256 + tid;        // 0..4095
            const int c = idx >> 6;                // token 0..63
            const int d = idx & 63;                // dim   0..63
            const float v = tf32r(vbase[(size_t)(kk0 + c) * DH + d]);
            const uint32_t byte = (uint32_t)d * 272u +
                                  (((uint32_t)c * 4u) ^ ((((uint32_t)d >> 3) & 3u) << 4));
            *(float*)((char*)VT + byte) = v;
        }
        // ---- adj tile into Ps ----
        const float* aptr = adj + ((size_t)b * T + q0g) * T + kk0;
#pragma unroll
        for (int it = 0; it < 8; it++) {
            const int idx = it * 256 + tid;
            const int r = idx >> 4, s = idx & 15;
            *(float4*)&Ps[r * ASS + s * 4] = *(const float4*)(aptr + (size_t)r * T + s * 4);
        }
        if (tid < 64) MS[tid] = mask[b * T + kk0 + tid];
        __syncthreads();

        // ---- S = Q @ K^T  (warp: 16 q x 64 c), 8 k-steps over DH ----
        float sacc[8][4];
#pragma unroll
        for (int tn = 0; tn < 8; tn++)
#pragma unroll
            for (int e = 0; e < 4; e++) sacc[tn][e] = 0.f;

#pragma unroll
        for (int ks = 0; ks < 8; ks++) {
            const uint32_t kb = (uint32_t)ks * 32u;
            uint32_t afr[4];
            LDMATRIX_X4(afr[0], afr[1], afr[2], afr[3], sQ + a_row_off + kb + a_khi);
            uint32_t bfr[4][4];
#pragma unroll
            for (int tp = 0; tp < 4; tp++) {
                const uint32_t addr = sK + (uint32_t)(tp * 16 + b_rl) * 272u + kb + b_khi;
                LDMATRIX_X4(bfr[tp][0], bfr[tp][1], bfr[tp][2], bfr[tp][3], addr);
            }
#pragma unroll
            for (int tn = 0; tn < 8; tn++)
                mma_tf32(sacc[tn], afr,
                         bfr[tn >> 1][(tn & 1) * 2 + 0],
                         bfr[tn >> 1][(tn & 1) * 2 + 1]);
        }

        // ---- softmax (adj*mask, online max/sum, P back to Ps as tf32) ----
#pragma unroll
        for (int hh = 0; hh < 2; hh++) {
            const int rq = q0 + (lane >> 2) + 8 * hh;
            float rowm = -1e30f;
#pragma unroll
            for (int tn = 0; tn < 8; tn++) {
                const int cc = tn * 8 + (lane & 3) * 2;
                const float2 a2 = *(const float2*)&Ps[rq * ASS + cc];
                const float2 m2 = *(const float2*)&MS[cc];
                float s0 = sacc[tn][2 * hh + 0] * a2.x * m2.x;
                float s1 = sacc[tn][2 * hh + 1] * a2.y * m2.y;
                sacc[tn][2 * hh + 0] = s0;
                sacc[tn][2 * hh + 1] = s1;
                rowm = fmaxf(rowm, fmaxf(s0, s1));
            }
            rowm = fmaxf(rowm, __shfl_xor_sync(0xffffffffu, rowm, 1));
            rowm = fmaxf(rowm, __shfl_xor_sync(0xffffffffu, rowm, 2));

            const float mnew  = fmaxf(mx[hh], rowm);
            const float alpha = __expf(mx[hh] - mnew);
            mx[hh] = mnew;
            l1[hh] *= alpha; l2[hh] *= alpha;
#pragma unroll
            for (int tn = 0; tn < 8; tn++) {
                oacc[tn][2 * hh + 0] *= alpha;
                oacc[tn][2 * hh + 1] *= alpha;
            }

            float s1s = 0.f, s2s = 0.f;
#pragma unroll
            for (int tn = 0; tn < 8; tn++) {
                const int cc = tn * 8 + (lane & 3) * 2;
                const float2 m2 = *(const float2*)&MS[cc];
                const float p0 = __expf(sacc[tn][2 * hh + 0] - mnew);
                const float p1 = __expf(sacc[tn][2 * hh + 1] - mnew);
                const float pm0 = p0 * m2.x;
                const float pm1 = p1 * m2.y;
                s2s += p0 + p1;
                s1s += pm0 + pm1;
                float2 pw;
                pw.x = tf32r(pm0);
                pw.y = tf32r(pm1);
                *(float2*)&Ps[rq * ASS + cc] = pw;
            }
            s1s += __shfl_xor_sync(0xffffffffu, s1s, 1);
            s1s += __shfl_xor_sync(0xffffffffu, s1s, 2);
            s2s += __shfl_xor_sync(0xffffffffu, s2s, 1);
            s2s += __shfl_xor_sync(0xffffffffu, s2s, 2);
            l1[hh] += s1s; l2[hh] += s2s;
        }
        __syncwarp();   // P stores visible to this warp's ldmatrix

        // ---- O += P @ V  (A = P rows q, k = c;  B = VT rows d, k = c) ----
#pragma unroll
        for (int cs = 0; cs < 8; cs++) {
            const uint32_t kb = (uint32_t)cs * 32u;
            uint32_t afr[4];
            LDMATRIX_X4(afr[0], afr[1], afr[2], afr[3], sP + a_row_off + kb + a_khi);
            uint32_t bfr[4][4];
#pragma unroll
            for (int tp = 0; tp < 4; tp++) {
                const uint32_t row = (uint32_t)(tp * 16 + b_rl);
                const uint32_t byteoff = (kb + b_khi) ^ (((row >> 3) & 3u) << 4);
                LDMATRIX_X4(bfr[tp][0], bfr[tp][1], bfr[tp][2], bfr[tp][3],
                            sV + row * 272u + byteoff);
            }
#pragma unroll
            for (int tn = 0; tn < 8; tn++)
                mma_tf32(oacc[tn], afr,
                         bfr[tn >> 1][(tn & 1) * 2 + 0],
                         bfr[tn >> 1][(tn & 1) * 2 + 1]);
        }
    }

    // ---- normalize and write ctx [B*T, D] with per-head column offset ----
#pragma unroll
    for (int hh = 0; hh < 2; hh++) {
        const float inv = 1.0f / (l1[hh] + EPS * l2[hh]);
        const int gq = q0g + q0 + (lane >> 2) + 8 * hh;
#pragma unroll
        for (int tn = 0; tn < 8; tn++) {
            const int d = tn * 8 + (lane & 3) * 2;
            float2 o;
            o.x = oacc[tn][2 * hh + 0] * inv;
            o.y = oacc[tn][2 * hh + 1] * inv;
            *(float2*)&g_ctx[(size_t)(b * T + gq) * D + h * DH + d] = o;
        }
    }
}

// ============================================================================
// launch
// ============================================================================
extern "C" void kernel_launch(void* const* d_in, const int* in_sizes, int n_in,
                              void* d_out, int out_size)
{
    (void)in_sizes; (void)n_in; (void)out_size;
    const float* inputs = (const float*)d_in[0];
    const float* mask   = (const float*)d_in[1];
    const float* adj    = (const float*)d_in[2];
    const float* W_qkv  = (const float*)d_in[3];
    const float* b_qkv  = (const float*)d_in[4];
    const float* W_out  = (const float*)d_in[5];
    const float* b_out  = (const float*)d_in[6];
    float* out = (float*)d_out;

    cudaFuncSetAttribute(gemm_mma_kernel<0>,
                         cudaFuncAttributeMaxDynamicSharedMemorySize,
                         GEMM_SMEM_BYTES);
    cudaFuncSetAttribute(gemm_mma_kernel<1>,
                         cudaFuncAttributeMaxDynamicSharedMemorySize,
                         GEMM_SMEM_BYTES);
    cudaFuncSetAttribute(attn_mma_kernel,
                         cudaFuncAttributeMaxDynamicSharedMemorySize,
                         ATTN_SMEM_BYTES);

    dim3 blk(256);
    // QKV projection: M=8192, N=3072, K=1024  (tf32 mma.sync)
    gemm_mma_kernel<0><<<dim3((3 * D) / 128, (B * T) / 128), blk, GEMM_SMEM_BYTES>>>(
        inputs, W_qkv, b_qkv, nullptr, D, 3 * D);

    // fused attention (tf32 mma.sync)
    attn_mma_kernel<<<dim3(T / AQT, H, B), blk, ATTN_SMEM_BYTES>>>(adj, mask);

    // output projection: M=8192, N=1024, K=1024  (tf32 mma.sync)
    gemm_mma_kernel<1><<<dim3(D / 128, (B * T) / 128), blk, GEMM_SMEM_BYTES>>>(
        nullptr, W_out, b_out, out, D, D);
}

// round 5
// speedup vs baseline: 3.1836x; 1.0995x over previous
#include <cuda_runtime.h>
#include <cstdint>

// ---------------- problem constants ----------------
constexpr int B  = 8;
constexpr int T  = 1024;
constexpr int D  = 1024;
constexpr int H  = 16;
constexpr int DH = 64;
constexpr float INV_SCALE = 0.125f;   // 1/sqrt(DH)
constexpr float EPS = 1e-13f;

// ---------------- scratch (device globals: no allocation allowed) ----------------
__device__ float g_q[(size_t)B * H * T * DH];   // 32 MB
__device__ float g_k[(size_t)B * H * T * DH];   // 32 MB
__device__ float g_v[(size_t)B * H * T * DH];   // 32 MB
__device__ float g_ctx[(size_t)B * T * D];      // 32 MB, [B*T, D] row-major (tf32-rounded)
__device__ float g_in_r[(size_t)B * T * D];     // 32 MB, tf32-rounded inputs
__device__ float g_wqkv_r[(size_t)3 * D * D];   // 12 MB, tf32-rounded W_qkv
__device__ float g_wout_r[(size_t)D * D];       //  4 MB, tf32-rounded W_out

// ---------------- PTX helpers (base-arch only) ----------------
__device__ __forceinline__ uint32_t smem_u32(const void* p) {
    uint32_t a;
    asm("{ .reg .u64 t; cvta.to.shared.u64 t, %1; cvt.u32.u64 %0, t; }"
        : "=r"(a) : "l"(p));
    return a;
}

#define CP_ASYNC16(dst, src) \
    asm volatile("cp.async.cg.shared.global [%0], [%1], 16;" :: "r"(dst), "l"(src))
#define CP_COMMIT()  asm volatile("cp.async.commit_group;" ::: "memory")
#define CP_WAIT(n)   asm volatile("cp.async.wait_group %0;" :: "n"(n) : "memory")

#define LDMATRIX_X4(r0, r1, r2, r3, addr) \
    asm volatile("ldmatrix.sync.aligned.m8n8.x4.shared.b16 {%0,%1,%2,%3}, [%4];" \
        : "=r"(r0), "=r"(r1), "=r"(r2), "=r"(r3) : "r"(addr))

__device__ __forceinline__ uint32_t f2tf32(uint32_t x) {
    uint32_t d;
    asm("cvt.rna.tf32.f32 %0, %1;" : "=r"(d) : "r"(x));
    return d;
}
__device__ __forceinline__ float tf32r(float x) {
    return __uint_as_float(f2tf32(__float_as_uint(x)));
}

__device__ __forceinline__ void mma_tf32(float* c, const uint32_t* a,
                                         uint32_t b0, uint32_t b1) {
    asm volatile(
        "mma.sync.aligned.m16n8k8.row.col.f32.tf32.tf32.f32 "
        "{%0,%1,%2,%3}, {%4,%5,%6,%7}, {%8,%9}, {%0,%1,%2,%3};"
        : "+f"(c[0]), "+f"(c[1]), "+f"(c[2]), "+f"(c[3])
        : "r"(a[0]), "r"(a[1]), "r"(a[2]), "r"(a[3]), "r"(b0), "r"(b1));
}

// ============================================================================
// tf32 pre-round pass: dst[i] = round_rna_tf32(src[i]).  float4 grid-stride.
// ============================================================================
__global__ void __launch_bounds__(256)
round_tf32_kernel(const float4* __restrict__ src, float4* __restrict__ dst, int n4)
{
    const int i = blockIdx.x * 256 + threadIdx.x;
    if (i < n4) {
        float4 v = src[i];
        v.x = tf32r(v.x); v.y = tf32r(v.y); v.z = tf32r(v.z); v.w = tf32r(v.w);
        dst[i] = v;
    }
}

// ============================================================================
// tf32 mma.sync GEMM (operands PRE-ROUNDED to tf32 in gmem -> no cvt in loop):
//   C[m,n] = sum_k A[m,k] * W[n,k] + bias[n]
// ============================================================================
constexpr int GBK = 32;
constexpr int G_TILE = 128 * 128;               // 16 KB
constexpr int GEMM_SMEM_BYTES = 4 * G_TILE;     // 64 KB

__device__ __forceinline__ void load_chunk(uint32_t sA, uint32_t sB,
                                           const float* __restrict__ Ab,
                                           const float* __restrict__ Wb,
                                           int K, int k0) {
    const int tid = threadIdx.x;
#pragma unroll
    for (int it = 0; it < 4; it++) {
        const int idx = it * 256 + tid;
        const int r = idx >> 3;
        const int s = idx & 7;
        const uint32_t off = (uint32_t)r * 128u + (((uint32_t)s * 16u) ^ (((uint32_t)r & 7u) << 4));
        CP_ASYNC16(sA + off, Ab + (size_t)r * K + k0 + s * 4);
    }
#pragma unroll
    for (int it = 0; it < 4; it++) {
        const int idx = it * 256 + tid;
        const int r = idx >> 3;
        const int s = idx & 7;
        const uint32_t off = (uint32_t)r * 128u + (((uint32_t)s * 16u) ^ (((uint32_t)r & 7u) << 4));
        CP_ASYNC16(sB + off, Wb + (size_t)r * K + k0 + s * 4);
    }
}

template <int MODE>
__global__ void __launch_bounds__(256)
gemm_mma_kernel(const float* __restrict__ A, const float* __restrict__ W,
                const float* __restrict__ bias, float* __restrict__ C,
                int K, int Ntot)
{
    extern __shared__ __align__(1024) char smem[];
    const uint32_t sbase = smem_u32(smem);
    const int tid  = threadIdx.x;
    const int wid  = tid >> 5;
    const int lane = tid & 31;

    const int m0 = blockIdx.y * 128;
    const int n0 = blockIdx.x * 128;

    const float* Asrc = (MODE == 1) ? (const float*)g_ctx : A;
    const float* Ab = Asrc + (size_t)m0 * K;
    const float* Wb = W    + (size_t)n0 * K;

    const uint32_t sA[2] = { sbase,          sbase + 2 * G_TILE };
    const uint32_t sB[2] = { sbase + G_TILE, sbase + 3 * G_TILE };

    const int wm = (wid >> 2) * 64;
    const int wn = (wid & 3) * 32;

    const int arow       = wm + (lane & 15);
    const uint32_t aoff  = (uint32_t)arow * 128u;
    const uint32_t aswz  = ((uint32_t)arow & 7u) << 4;
    const uint32_t akhi  = (uint32_t)(lane & 16);
    const int brow       = wn + (lane & 7) + ((lane & 16) >> 1);
    const uint32_t boff  = (uint32_t)brow * 128u;
    const uint32_t bswz  = ((uint32_t)brow & 7u) << 4;
    const uint32_t bkhi  = (uint32_t)((lane & 8) << 1);

    float acc[4][4][4];
#pragma unroll
    for (int i = 0; i < 4; i++)
#pragma unroll
        for (int j = 0; j < 4; j++)
#pragma unroll
            for (int e = 0; e < 4; e++) acc[i][j][e] = 0.f;

    const int NC = K / GBK;
    load_chunk(sA[0], sB[0], Ab, Wb, K, 0);
    CP_COMMIT();

    for (int i = 0; i < NC; i++) {
        const int bsel = i & 1;
        if (i + 1 < NC) {
            load_chunk(sA[1 - bsel], sB[1 - bsel], Ab, Wb, K, (i + 1) * GBK);
            CP_COMMIT();
            CP_WAIT(1);
        } else {
            CP_WAIT(0);
        }
        __syncthreads();

        const uint32_t aB = sA[bsel];
        const uint32_t bB = sB[bsel];

#pragma unroll
        for (int ks = 0; ks < 4; ks++) {
            const uint32_t kb = (uint32_t)ks * 32u;
            uint32_t afr[4][4];
#pragma unroll
            for (int tm = 0; tm < 4; tm++) {
                const uint32_t addr = aB + aoff + (uint32_t)tm * 2048u + ((kb + akhi) ^ aswz);
                LDMATRIX_X4(afr[tm][0], afr[tm][1], afr[tm][2], afr[tm][3], addr);
            }
            uint32_t bfr[2][4];
#pragma unroll
            for (int tp = 0; tp < 2; tp++) {
                const uint32_t addr = bB + boff + (uint32_t)tp * 2048u + ((kb + bkhi) ^ bswz);
                LDMATRIX_X4(bfr[tp][0], bfr[tp][1], bfr[tp][2], bfr[tp][3], addr);
            }
            // operands pre-rounded to tf32: no cvt needed here
#pragma unroll
            for (int tm = 0; tm < 4; tm++)
#pragma unroll
                for (int tn = 0; tn < 4; tn++)
                    mma_tf32(acc[tm][tn], afr[tm],
                             bfr[tn >> 1][(tn & 1) * 2 + 0],
                             bfr[tn >> 1][(tn & 1) * 2 + 1]);
        }
        __syncthreads();
    }

#pragma unroll
    for (int tm = 0; tm < 4; tm++) {
#pragma unroll
        for (int tn = 0; tn < 4; tn++) {
            const int col = n0 + wn + tn * 8 + (lane & 3) * 2;
            const float bx = bias[col], by = bias[col + 1];
#pragma unroll
            for (int half = 0; half < 2; half++) {
                const int row = m0 + wm + tm * 16 + (lane >> 2) + half * 8;
                float2 v;
                v.x = acc[tm][tn][half * 2 + 0] + bx;
                v.y = acc[tm][tn][half * 2 + 1] + by;
                if (MODE == 0) {
                    // pre-round so the attention kernel needs no cvts
                    v.x = tf32r(v.x); v.y = tf32r(v.y);
                    const int sel = col >> 10;
                    float* dst = (sel == 0) ? g_q : (sel == 1) ? g_k : g_v;
                    const int bb = row >> 10;
                    const int t  = row & 1023;
                    const int hh = (col & 1023) >> 6;
                    const int d  = col & 63;
                    *(float2*)&dst[((size_t)(bb * H + hh) * T + t) * DH + d] = v;
                } else {
                    *(float2*)&C[(size_t)row * Ntot + col] = v;
                }
            }
        }
    }
}

// ============================================================================
// Fused flash attention on tensor cores (tf32 mma.sync).
//   Q/K/V arrive pre-rounded to tf32 (GEMM1 epilogue). INV_SCALE is a power
//   of two, so scaling preserves tf32-ness.
// ============================================================================
constexpr int AQT = 128;
constexpr int AKT = 64;
constexpr int ASS = 68;                              // row stride in floats
constexpr int ATTN_SMEM_BYTES =
    (AQT * ASS + AKT * ASS + AKT * ASS + AQT * ASS + AKT) * 4;  // 104,704 B

__global__ void __launch_bounds__(256, 2)
attn_mma_kernel(const float* __restrict__ adj, const float* __restrict__ mask)
{
    extern __shared__ __align__(16) float sh[];
    float* Qs = sh;                    // [128][68] Q, tf32, pre-scaled
    float* Ks = Qs + AQT * ASS;        // [64][68]  K rows=c cols=d, tf32
    float* VT = Ks + AKT * ASS;        // [64][68]  rows=d cols=c (chunk-XOR), tf32
    float* Ps = VT + AKT * ASS;        // [128][68] adj tile, then P (tf32)
    float* MS = Ps + AQT * ASS;        // [64]

    const int b   = blockIdx.z;
    const int h   = blockIdx.y;
    const int q0g = blockIdx.x * AQT;
    const int tid = threadIdx.x;
    const int wid = tid >> 5;
    const int lane = tid & 31;
    const int q0  = wid * 16;                        // warp's q-row base (block-local)

    const float* qptr  = g_q + ((size_t)(b * H + h) * T + q0g) * DH;
    const float* kbase = g_k + (size_t)(b * H + h) * T * DH;
    const float* vbase = g_v + (size_t)(b * H + h) * T * DH;

    const uint32_t sQ = smem_u32(Qs);
    const uint32_t sK = smem_u32(Ks);
    const uint32_t sV = smem_u32(VT);
    const uint32_t sP = smem_u32(Ps);

    // ---- load Q once: scale by exact power of two (stays tf32) ----
#pragma unroll
    for (int it = 0; it < 8; it++) {
        const int idx = it * 256 + tid;
        const int r = idx >> 4, s = idx & 15;
        float4 v = *(const float4*)(qptr + (size_t)r * DH + s * 4);
        v.x *= INV_SCALE; v.y *= INV_SCALE; v.z *= INV_SCALE; v.w *= INV_SCALE;
        *(float4*)&Qs[r * ASS + s * 4] = v;
    }

    // fragment lane addressing (byte offsets; verified mapping)
    const uint32_t a_row_off = (uint32_t)(q0 + (lane & 15)) * 272u;
    const uint32_t a_khi     = (uint32_t)(lane & 16);
    const int      b_rl      = (lane & 7) + ((lane & 16) >> 1);
    const uint32_t b_khi     = (uint32_t)((lane & 8) << 1);

    float oacc[8][4];
#pragma unroll
    for (int tn = 0; tn < 8; tn++)
#pragma unroll
        for (int e = 0; e < 4; e++) oacc[tn][e] = 0.f;
    float mx[2] = { -1e30f, -1e30f };
    float l1[2] = { 0.f, 0.f };
    float l2[2] = { 0.f, 0.f };

    for (int kt = 0; kt < T / AKT; kt++) {
        const int kk0 = kt * AKT;
        __syncthreads();   // previous tile fully consumed

        // ---- K tile: LDG.128 -> STS.128 (already tf32) ----
#pragma unroll
        for (int it = 0; it < 4; it++) {
            const int idx = it * 256 + tid;
            const int r = idx >> 4, s = idx & 15;
            float4 v = *(const float4*)(kbase + (size_t)(kk0 + r) * DH + s * 4);
            *(float4*)&Ks[r * ASS + s * 4] = v;
        }
        // ---- V tile transposed: coalesced LDG.32, conflict-free STS.32 ----
#pragma unroll
        for (int it = 0; it < 16; it++) {
            const int idx = it * 256 + tid;        // 0..4095
            const int c = idx >> 6;                // token 0..63
            const int d = idx & 63;                // dim   0..63
            const float v = vbase[(size_t)(kk0 + c) * DH + d];
            const uint32_t byte = (uint32_t)d * 272u +
                                  (((uint32_t)c * 4u) ^ ((((uint32_t)d >> 3) & 3u) << 4));
            *(float*)((char*)VT + byte) = v;
        }
        // ---- adj tile into Ps ----
        const float* aptr = adj + ((size_t)b * T + q0g) * T + kk0;
#pragma unroll
        for (int it = 0; it < 8; it++) {
            const int idx = it * 256 + tid;
            const int r = idx >> 4, s = idx & 15;
            *(float4*)&Ps[r * ASS + s * 4] = *(const float4*)(aptr + (size_t)r * T + s * 4);
        }
        if (tid < 64) MS[tid] = mask[b * T + kk0 + tid];
        __syncthreads();

        // ---- S = Q @ K^T  (warp: 16 q x 64 c), 8 k-steps over DH ----
        float sacc[8][4];
#pragma unroll
        for (int tn = 0; tn < 8; tn++)
#pragma unroll
            for (int e = 0; e < 4; e++) sacc[tn][e] = 0.f;

#pragma unroll
        for (int ks = 0; ks < 8; ks++) {
            const uint32_t kb = (uint32_t)ks * 32u;
            uint32_t afr[4];
            LDMATRIX_X4(afr[0], afr[1], afr[2], afr[3], sQ + a_row_off + kb + a_khi);
            uint32_t bfr[4][4];
#pragma unroll
            for (int tp = 0; tp < 4; tp++) {
                const uint32_t addr = sK + (uint32_t)(tp * 16 + b_rl) * 272u + kb + b_khi;
                LDMATRIX_X4(bfr[tp][0], bfr[tp][1], bfr[tp][2], bfr[tp][3], addr);
            }
#pragma unroll
            for (int tn = 0; tn < 8; tn++)
                mma_tf32(sacc[tn], afr,
                         bfr[tn >> 1][(tn & 1) * 2 + 0],
                         bfr[tn >> 1][(tn & 1) * 2 + 1]);
        }

        // ---- softmax (adj*mask, online max/sum, P back to Ps as tf32) ----
#pragma unroll
        for (int hh = 0; hh < 2; hh++) {
            const int rq = q0 + (lane >> 2) + 8 * hh;
            float rowm = -1e30f;
#pragma unroll
            for (int tn = 0; tn < 8; tn++) {
                const int cc = tn * 8 + (lane & 3) * 2;
                const float2 a2 = *(const float2*)&Ps[rq * ASS + cc];
                const float2 m2 = *(const float2*)&MS[cc];
                float s0 = sacc[tn][2 * hh + 0] * a2.x * m2.x;
                float s1 = sacc[tn][2 * hh + 1] * a2.y * m2.y;
                sacc[tn][2 * hh + 0] = s0;
                sacc[tn][2 * hh + 1] = s1;
                rowm = fmaxf(rowm, fmaxf(s0, s1));
            }
            rowm = fmaxf(rowm, __shfl_xor_sync(0xffffffffu, rowm, 1));
            rowm = fmaxf(rowm, __shfl_xor_sync(0xffffffffu, rowm, 2));

            const float mnew  = fmaxf(mx[hh], rowm);
            const float alpha = __expf(mx[hh] - mnew);
            mx[hh] = mnew;
            l1[hh] *= alpha; l2[hh] *= alpha;
#pragma unroll
            for (int tn = 0; tn < 8; tn++) {
                oacc[tn][2 * hh + 0] *= alpha;
                oacc[tn][2 * hh + 1] *= alpha;
            }

            float s1s = 0.f, s2s = 0.f;
#pragma unroll
            for (int tn = 0; tn < 8; tn++) {
                const int cc = tn * 8 + (lane & 3) * 2;
                const float2 m2 = *(const float2*)&MS[cc];
                const float p0 = __expf(sacc[tn][2 * hh + 0] - mnew);
                const float p1 = __expf(sacc[tn][2 * hh + 1] - mnew);
                const float pm0 = p0 * m2.x;
                const float pm1 = p1 * m2.y;
                s2s += p0 + p1;
                s1s += pm0 + pm1;
                float2 pw;
                pw.x = tf32r(pm0);
                pw.y = tf32r(pm1);
                *(float2*)&Ps[rq * ASS + cc] = pw;
            }
            s1s += __shfl_xor_sync(0xffffffffu, s1s, 1);
            s1s += __shfl_xor_sync(0xffffffffu, s1s, 2);
            s2s += __shfl_xor_sync(0xffffffffu, s2s, 1);
            s2s += __shfl_xor_sync(0xffffffffu, s2s, 2);
            l1[hh] += s1s; l2[hh] += s2s;
        }
        __syncwarp();   // P stores visible to this warp's ldmatrix

        // ---- O += P @ V  (A = P rows q, k = c;  B = VT rows d, k = c) ----
#pragma unroll
        for (int cs = 0; cs < 8; cs++) {
            const uint32_t kb = (uint32_t)cs * 32u;
            uint32_t afr[4];
            LDMATRIX_X4(afr[0], afr[1], afr[2], afr[3], sP + a_row_off + kb + a_khi);
            uint32_t bfr[4][4];
#pragma unroll
            for (int tp = 0; tp < 4; tp++) {
                const uint32_t row = (uint32_t)(tp * 16 + b_rl);
                const uint32_t byteoff = (kb + b_khi) ^ (((row >> 3) & 3u) << 4);
                LDMATRIX_X4(bfr[tp][0], bfr[tp][1], bfr[tp][2], bfr[tp][3],
                            sV + row * 272u + byteoff);
            }
#pragma unroll
            for (int tn = 0; tn < 8; tn++)
                mma_tf32(oacc[tn], afr,
                         bfr[tn >> 1][(tn & 1) * 2 + 0],
                         bfr[tn >> 1][(tn & 1) * 2 + 1]);
        }
    }

    // ---- normalize, tf32-round (GEMM2 consumes raw), write ctx ----
#pragma unroll
    for (int hh = 0; hh < 2; hh++) {
        const float inv = 1.0f / (l1[hh] + EPS * l2[hh]);
        const int gq = q0g + q0 + (lane >> 2) + 8 * hh;
#pragma unroll
        for (int tn = 0; tn < 8; tn++) {
            const int d = tn * 8 + (lane & 3) * 2;
            float2 o;
            o.x = tf32r(oacc[tn][2 * hh + 0] * inv);
            o.y = tf32r(oacc[tn][2 * hh + 1] * inv);
            *(float2*)&g_ctx[(size_t)(b * T + gq) * D + h * DH + d] = o;
        }
    }
}

// ============================================================================
// launch
// ============================================================================
extern "C" void kernel_launch(void* const* d_in, const int* in_sizes, int n_in,
                              void* d_out, int out_size)
{
    (void)in_sizes; (void)n_in; (void)out_size;
    const float* inputs = (const float*)d_in[0];
    const float* mask   = (const float*)d_in[1];
    const float* adj    = (const float*)d_in[2];
    const float* W_qkv  = (const float*)d_in[3];
    const float* b_qkv  = (const float*)d_in[4];
    const float* W_out  = (const float*)d_in[5];
    const float* b_out  = (const float*)d_in[6];
    float* out = (float*)d_out;

    cudaFuncSetAttribute(gemm_mma_kernel<0>,
                         cudaFuncAttributeMaxDynamicSharedMemorySize,
                         GEMM_SMEM_BYTES);
    cudaFuncSetAttribute(gemm_mma_kernel<1>,
                         cudaFuncAttributeMaxDynamicSharedMemorySize,
                         GEMM_SMEM_BYTES);
    cudaFuncSetAttribute(attn_mma_kernel,
                         cudaFuncAttributeMaxDynamicSharedMemorySize,
                         ATTN_SMEM_BYTES);

    // resolve device-global addresses (host-side; graph-capture safe)
    float *p_in_r, *p_wqkv_r, *p_wout_r;
    cudaGetSymbolAddress((void**)&p_in_r,   g_in_r);
    cudaGetSymbolAddress((void**)&p_wqkv_r, g_wqkv_r);
    cudaGetSymbolAddress((void**)&p_wout_r, g_wout_r);

    dim3 blk(256);

    // tf32 pre-round pass (removes all cvts from GEMM hot loops)
    {
        const int n4_in   = (B * T * D) / 4;       // 2,097,152
        const int n4_wqkv = (3 * D * D) / 4;       //   786,432
        const int n4_wout = (D * D) / 4;           //   262,144
        round_tf32_kernel<<<(n4_in   + 255) / 256, blk>>>((const float4*)inputs, (float4*)p_in_r,   n4_in);
        round_tf32_kernel<<<(n4_wqkv + 255) / 256, blk>>>((const float4*)W_qkv,  (float4*)p_wqkv_r, n4_wqkv);
        round_tf32_kernel<<<(n4_wout + 255) / 256, blk>>>((const float4*)W_out,  (float4*)p_wout_r, n4_wout);
    }

    // QKV projection: M=8192, N=3072, K=1024  (tf32 mma.sync, pre-rounded)
    gemm_mma_kernel<0><<<dim3((3 * D) / 128, (B * T) / 128), blk, GEMM_SMEM_BYTES>>>(
        p_in_r, p_wqkv_r, b_qkv, nullptr, D, 3 * D);

    // fused attention (tf32 mma.sync)
    attn_mma_kernel<<<dim3(T / AQT, H, B), blk, ATTN_SMEM_BYTES>>>(adj, mask);

    // output projection: M=8192, N=1024, K=1024  (tf32 mma.sync, pre-rounded)
    gemm_mma_kernel<1><<<dim3(D / 128, (B * T) / 128), blk, GEMM_SMEM_BYTES>>>(
        nullptr, p_wout_r, b_out, out, D, D);
}

// round 6
// speedup vs baseline: 3.2152x; 1.0099x over previous
#include <cuda_runtime.h>
#include <cstdint>

// ---------------- problem constants ----------------
constexpr int B  = 8;
constexpr int T  = 1024;
constexpr int D  = 1024;
constexpr int H  = 16;
constexpr int DH = 64;
constexpr float INV_SCALE = 0.125f;   // 1/sqrt(DH)
constexpr float EPS = 1e-13f;

// ---------------- scratch (device globals: no allocation allowed) ----------------
__device__ float g_q[(size_t)B * H * T * DH];   // 32 MB
__device__ float g_k[(size_t)B * H * T * DH];   // 32 MB
__device__ float g_v[(size_t)B * H * T * DH];   // 32 MB
__device__ float g_ctx[(size_t)B * T * D];      // 32 MB, [B*T, D] row-major (tf32-rounded)
__device__ float g_in_r[(size_t)B * T * D];     // 32 MB, tf32-rounded inputs
__device__ float g_wqkv_r[(size_t)3 * D * D];   // 12 MB, tf32-rounded W_qkv
__device__ float g_wout_r[(size_t)D * D];       //  4 MB, tf32-rounded W_out

// ---------------- PTX helpers (base-arch only) ----------------
__device__ __forceinline__ uint32_t smem_u32(const void* p) {
    uint32_t a;
    asm("{ .reg .u64 t; cvta.to.shared.u64 t, %1; cvt.u32.u64 %0, t; }"
        : "=r"(a) : "l"(p));
    return a;
}

#define CP_ASYNC16(dst, src) \
    asm volatile("cp.async.cg.shared.global [%0], [%1], 16;" :: "r"(dst), "l"(src))
#define CP_COMMIT()  asm volatile("cp.async.commit_group;" ::: "memory")
#define CP_WAIT(n)   asm volatile("cp.async.wait_group %0;" :: "n"(n) : "memory")

#define LDMATRIX_X4(r0, r1, r2, r3, addr) \
    asm volatile("ldmatrix.sync.aligned.m8n8.x4.shared.b16 {%0,%1,%2,%3}, [%4];" \
        : "=r"(r0), "=r"(r1), "=r"(r2), "=r"(r3) : "r"(addr))

__device__ __forceinline__ uint32_t f2tf32(uint32_t x) {
    uint32_t d;
    asm("cvt.rna.tf32.f32 %0, %1;" : "=r"(d) : "r"(x));
    return d;
}
__device__ __forceinline__ float tf32r(float x) {
    return __uint_as_float(f2tf32(__float_as_uint(x)));
}

__device__ __forceinline__ void mma_tf32(float* c, const uint32_t* a,
                                         uint32_t b0, uint32_t b1) {
    asm volatile(
        "mma.sync.aligned.m16n8k8.row.col.f32.tf32.tf32.f32 "
        "{%0,%1,%2,%3}, {%4,%5,%6,%7}, {%8,%9}, {%0,%1,%2,%3};"
        : "+f"(c[0]), "+f"(c[1]), "+f"(c[2]), "+f"(c[3])
        : "r"(a[0]), "r"(a[1]), "r"(a[2]), "r"(a[3]), "r"(b0), "r"(b1));
}

// ============================================================================
// tf32 pre-round pass: dst[i] = round_rna_tf32(src[i]).
// ============================================================================
__global__ void __launch_bounds__(256)
round_tf32_kernel(const float4* __restrict__ src, float4* __restrict__ dst, int n4)
{
    const int i = blockIdx.x * 256 + threadIdx.x;
    if (i < n4) {
        float4 v = src[i];
        v.x = tf32r(v.x); v.y = tf32r(v.y); v.z = tf32r(v.z); v.w = tf32r(v.w);
        dst[i] = v;
    }
}

// ============================================================================
// tf32 mma.sync GEMM, 3-stage cp.async pipeline (race-free, 1 barrier/chunk):
//   C[m,n] = sum_k A[m,k] * W[n,k] + bias[n]
// ============================================================================
constexpr int GBK = 32;
constexpr int G_TILE  = 128 * 128;              // 16 KB per operand tile
constexpr int G_STAGE = 2 * G_TILE;             // A + B per stage = 32 KB
constexpr int GEMM_SMEM_BYTES = 3 * G_STAGE;    // 96 KB (2 CTAs/SM fits)

__device__ __forceinline__ void load_chunk(uint32_t sA, uint32_t sB,
                                           const float* __restrict__ Ab,
                                           const float* __restrict__ Wb,
                                           int K, int k0) {
    const int tid = threadIdx.x;
#pragma unroll
    for (int it = 0; it < 4; it++) {
        const int idx = it * 256 + tid;
        const int r = idx >> 3;
        const int s = idx & 7;
        const uint32_t off = (uint32_t)r * 128u + (((uint32_t)s * 16u) ^ (((uint32_t)r & 7u) << 4));
        CP_ASYNC16(sA + off, Ab + (size_t)r * K + k0 + s * 4);
    }
#pragma unroll
    for (int it = 0; it < 4; it++) {
        const int idx = it * 256 + tid;
        const int r = idx >> 3;
        const int s = idx & 7;
        const uint32_t off = (uint32_t)r * 128u + (((uint32_t)s * 16u) ^ (((uint32_t)r & 7u) << 4));
        CP_ASYNC16(sB + off, Wb + (size_t)r * K + k0 + s * 4);
    }
}

template <int MODE>
__global__ void __launch_bounds__(256)
gemm_mma_kernel(const float* __restrict__ A, const float* __restrict__ W,
                const float* __restrict__ bias, float* __restrict__ C,
                int K, int Ntot)
{
    extern __shared__ __align__(1024) char smem[];
    const uint32_t sbase = smem_u32(smem);
    const int tid  = threadIdx.x;
    const int wid  = tid >> 5;
    const int lane = tid & 31;

    const int m0 = blockIdx.y * 128;
    const int n0 = blockIdx.x * 128;

    const float* Asrc = (MODE == 1) ? (const float*)g_ctx : A;
    const float* Ab = Asrc + (size_t)m0 * K;
    const float* Wb = W    + (size_t)n0 * K;

    uint32_t sA[3], sB[3];
    uint64_t adesc[3], bdesc[3];
#pragma unroll
    for (int s = 0; s < 3; s++) {
        sA[s] = sbase + s * G_STAGE;
        sB[s] = sA[s] + G_TILE;
        adesc[s] = (uint64_t)sA[s];
        bdesc[s] = (uint64_t)sB[s];
    }

    const int wm = (wid >> 2) * 64;
    const int wn = (wid & 3) * 32;

    const int arow       = wm + (lane & 15);
    const uint32_t aoff  = (uint32_t)arow * 128u;
    const uint32_t aswz  = ((uint32_t)arow & 7u) << 4;
    const uint32_t akhi  = (uint32_t)(lane & 16);
    const int brow       = wn + (lane & 7) + ((lane & 16) >> 1);
    const uint32_t boff  = (uint32_t)brow * 128u;
    const uint32_t bswz  = ((uint32_t)brow & 7u) << 4;
    const uint32_t bkhi  = (uint32_t)((lane & 8) << 1);

    float acc[4][4][4];
#pragma unroll
    for (int i = 0; i < 4; i++)
#pragma unroll
        for (int j = 0; j < 4; j++)
#pragma unroll
            for (int e = 0; e < 4; e++) acc[i][j][e] = 0.f;

    const int NC = K / GBK;

    // prologue: stages 0,1 in flight
    load_chunk(sA[0], sB[0], Ab, Wb, K, 0);
    CP_COMMIT();
    load_chunk(sA[1], sB[1], Ab, Wb, K, GBK);
    CP_COMMIT();

    int st = 0;                       // stage holding chunk i
    for (int i = 0; i < NC; i++) {
        CP_WAIT(1);                   // chunk i data resident
        __syncthreads();              // visible to all; prior compute (i-1) done

        // prefetch chunk i+2 into the stage freed by compute i-1.
        // Always commit (possibly empty group) so CP_WAIT(1) semantics hold.
        const int pst = (st + 2 >= 3) ? st + 2 - 3 : st + 2;
        if (i + 2 < NC)
            load_chunk(sA[pst], sB[pst], Ab, Wb, K, (i + 2) * GBK);
        CP_COMMIT();

        const uint32_t aB = (uint32_t)adesc[st];
        const uint32_t bB = (uint32_t)bdesc[st];

#pragma unroll
        for (int ks = 0; ks < 4; ks++) {
            const uint32_t kb = (uint32_t)ks * 32u;
            uint32_t afr[4][4];
#pragma unroll
            for (int tm = 0; tm < 4; tm++) {
                const uint32_t addr = aB + aoff + (uint32_t)tm * 2048u + ((kb + akhi) ^ aswz);
                LDMATRIX_X4(afr[tm][0], afr[tm][1], afr[tm][2], afr[tm][3], addr);
            }
            uint32_t bfr[2][4];
#pragma unroll
            for (int tp = 0; tp < 2; tp++) {
                const uint32_t addr = bB + boff + (uint32_t)tp * 2048u + ((kb + bkhi) ^ bswz);
                LDMATRIX_X4(bfr[tp][0], bfr[tp][1], bfr[tp][2], bfr[tp][3], addr);
            }
#pragma unroll
            for (int tm = 0; tm < 4; tm++)
#pragma unroll
                for (int tn = 0; tn < 4; tn++)
                    mma_tf32(acc[tm][tn], afr[tm],
                             bfr[tn >> 1][(tn & 1) * 2 + 0],
                             bfr[tn >> 1][(tn & 1) * 2 + 1]);
        }
        st = (st + 1 >= 3) ? 0 : st + 1;
    }

#pragma unroll
    for (int tm = 0; tm < 4; tm++) {
#pragma unroll
        for (int tn = 0; tn < 4; tn++) {
            const int col = n0 + wn + tn * 8 + (lane & 3) * 2;
            const float bx = bias[col], by = bias[col + 1];
#pragma unroll
            for (int half = 0; half < 2; half++) {
                const int row = m0 + wm + tm * 16 + (lane >> 2) + half * 8;
                float2 v;
                v.x = acc[tm][tn][half * 2 + 0] + bx;
                v.y = acc[tm][tn][half * 2 + 1] + by;
                if (MODE == 0) {
                    v.x = tf32r(v.x); v.y = tf32r(v.y);   // attn consumes tf32
                    const int sel = col >> 10;
                    float* dst = (sel == 0) ? g_q : (sel == 1) ? g_k : g_v;
                    const int bb = row >> 10;
                    const int t  = row & 1023;
                    const int hh = (col & 1023) >> 6;
                    const int d  = col & 63;
                    *(float2*)&dst[((size_t)(bb * H + hh) * T + t) * DH + d] = v;
                } else {
                    *(float2*)&C[(size_t)row * Ntot + col] = v;
                }
            }
        }
    }
}

// ============================================================================
// Fused flash attention on tensor cores (tf32 mma.sync), max-free softmax.
//   scores s = (q.k/8)*adj*mask have |s| << 88, so exp(s) cannot overflow:
//   out = sum e^s * m * V / (sum e^s * m + EPS * sum e^s)  — exact reference
//   algebra with the max-shift removed (it cancels identically).
// ============================================================================
constexpr int AQT = 128;
constexpr int AKT = 64;
constexpr int ASS = 68;                              // row stride in floats
constexpr int ATTN_SMEM_BYTES =
    (AQT * ASS + AKT * ASS + AKT * ASS + AQT * ASS + AKT) * 4;  // 104,704 B

__global__ void __launch_bounds__(256, 2)
attn_mma_kernel(const float* __restrict__ adj, const float* __restrict__ mask)
{
    extern __shared__ __align__(16) float sh[];
    float* Qs = sh;                    // [128][68] Q, tf32, pre-scaled
    float* Ks = Qs + AQT * ASS;        // [64][68]  K rows=c cols=d, tf32
    float* VT = Ks + AKT * ASS;        // [64][68]  rows=d cols=c (chunk-XOR), tf32
    float* Ps = VT + AKT * ASS;        // [128][68] adj tile, then P (tf32)
    float* MS = Ps + AQT * ASS;        // [64]

    const int b   = blockIdx.z;
    const int h   = blockIdx.y;
    const int q0g = blockIdx.x * AQT;
    const int tid = threadIdx.x;
    const int wid = tid >> 5;
    const int lane = tid & 31;
    const int q0  = wid * 16;                        // warp's q-row base (block-local)

    const float* qptr  = g_q + ((size_t)(b * H + h) * T + q0g) * DH;
    const float* kbase = g_k + (size_t)(b * H + h) * T * DH;
    const float* vbase = g_v + (size_t)(b * H + h) * T * DH;

    const uint32_t sQ = smem_u32(Qs);
    const uint32_t sK = smem_u32(Ks);
    const uint32_t sV = smem_u32(VT);
    const uint32_t sP = smem_u32(Ps);

    // ---- load Q once: scale by exact power of two (stays tf32) ----
#pragma unroll
    for (int it = 0; it < 8; it++) {
        const int idx = it * 256 + tid;
        const int r = idx >> 4, s = idx & 15;
        float4 v = *(const float4*)(qptr + (size_t)r * DH + s * 4);
        v.x *= INV_SCALE; v.y *= INV_SCALE; v.z *= INV_SCALE; v.w *= INV_SCALE;
        *(float4*)&Qs[r * ASS + s * 4] = v;
    }

    // fragment lane addressing (byte offsets; verified mapping)
    const uint32_t a_row_off = (uint32_t)(q0 + (lane & 15)) * 272u;
    const uint32_t a_khi     = (uint32_t)(lane & 16);
    const int      b_rl      = (lane & 7) + ((lane & 16) >> 1);
    const uint32_t b_khi     = (uint32_t)((lane & 8) << 1);

    float oacc[8][4];
#pragma unroll
    for (int tn = 0; tn < 8; tn++)
#pragma unroll
        for (int e = 0; e < 4; e++) oacc[tn][e] = 0.f;
    float l1[2] = { 0.f, 0.f };
    float l2[2] = { 0.f, 0.f };

    for (int kt = 0; kt < T / AKT; kt++) {
        const int kk0 = kt * AKT;
        __syncthreads();   // previous tile fully consumed

        // ---- K tile: LDG.128 -> STS.128 (already tf32) ----
#pragma unroll
        for (int it = 0; it < 4; it++) {
            const int idx = it * 256 + tid;
            const int r = idx >> 4, s = idx & 15;
            float4 v = *(const float4*)(kbase + (size_t)(kk0 + r) * DH + s * 4);
            *(float4*)&Ks[r * ASS + s * 4] = v;
        }
        // ---- V tile transposed: coalesced LDG.32, conflict-free STS.32 ----
#pragma unroll
        for (int it = 0; it < 16; it++) {
            const int idx = it * 256 + tid;        // 0..4095
            const int c = idx >> 6;                // token 0..63
            const int d = idx & 63;                // dim   0..63
            const float v = vbase[(size_t)(kk0 + c) * DH + d];
            const uint32_t byte = (uint32_t)d * 272u +
                                  (((uint32_t)c * 4u) ^ ((((uint32_t)d >> 3) & 3u) << 4));
            *(float*)((char*)VT + byte) = v;
        }
        // ---- adj tile into Ps ----
        const float* aptr = adj + ((size_t)b * T + q0g) * T + kk0;
#pragma unroll
        for (int it = 0; it < 8; it++) {
            const int idx = it * 256 + tid;
            const int r = idx >> 4, s = idx & 15;
            *(float4*)&Ps[r * ASS + s * 4] = *(const float4*)(aptr + (size_t)r * T + s * 4);
        }
        if (tid < 64) MS[tid] = mask[b * T + kk0 + tid];
        __syncthreads();

        // ---- S = Q @ K^T  (warp: 16 q x 64 c), 8 k-steps over DH ----
        float sacc[8][4];
#pragma unroll
        for (int tn = 0; tn < 8; tn++)
#pragma unroll
            for (int e = 0; e < 4; e++) sacc[tn][e] = 0.f;

#pragma unroll
        for (int ks = 0; ks < 8; ks++) {
            const uint32_t kb = (uint32_t)ks * 32u;
            uint32_t afr[4];
            LDMATRIX_X4(afr[0], afr[1], afr[2], afr[3], sQ + a_row_off + kb + a_khi);
            uint32_t bfr[4][4];
#pragma unroll
            for (int tp = 0; tp < 4; tp++) {
                const uint32_t addr = sK + (uint32_t)(tp * 16 + b_rl) * 272u + kb + b_khi;
                LDMATRIX_X4(bfr[tp][0], bfr[tp][1], bfr[tp][2], bfr[tp][3], addr);
            }
#pragma unroll
            for (int tn = 0; tn < 8; tn++)
                mma_tf32(sacc[tn], afr,
                         bfr[tn >> 1][(tn & 1) * 2 + 0],
                         bfr[tn >> 1][(tn & 1) * 2 + 1]);
        }

        // ---- max-free softmax: p = exp(s*adj*m), P -> Ps (tf32), sums ----
#pragma unroll
        for (int hh = 0; hh < 2; hh++) {
            const int rq = q0 + (lane >> 2) + 8 * hh;
            float s1s = 0.f, s2s = 0.f;
#pragma unroll
            for (int tn = 0; tn < 8; tn++) {
                const int cc = tn * 8 + (lane & 3) * 2;
                const float2 a2 = *(const float2*)&Ps[rq * ASS + cc];
                const float2 m2 = *(const float2*)&MS[cc];
                const float p0 = __expf(sacc[tn][2 * hh + 0] * a2.x * m2.x);
                const float p1 = __expf(sacc[tn][2 * hh + 1] * a2.y * m2.y);
                const float pm0 = p0 * m2.x;
                const float pm1 = p1 * m2.y;
                s2s += p0 + p1;
                s1s += pm0 + pm1;
                float2 pw;
                pw.x = tf32r(pm0);
                pw.y = tf32r(pm1);
                *(float2*)&Ps[rq * ASS + cc] = pw;
            }
            s1s += __shfl_xor_sync(0xffffffffu, s1s, 1);
            s1s += __shfl_xor_sync(0xffffffffu, s1s, 2);
            s2s += __shfl_xor_sync(0xffffffffu, s2s, 1);
            s2s += __shfl_xor_sync(0xffffffffu, s2s, 2);
            l1[hh] += s1s; l2[hh] += s2s;
        }
        __syncwarp();   // P stores visible to this warp's ldmatrix

        // ---- O += P @ V  (A = P rows q, k = c;  B = VT rows d, k = c) ----
#pragma unroll
        for (int cs = 0; cs < 8; cs++) {
            const uint32_t kb = (uint32_t)cs * 32u;
            uint32_t afr[4];
            LDMATRIX_X4(afr[0], afr[1], afr[2], afr[3], sP + a_row_off + kb + a_khi);
            uint32_t bfr[4][4];
#pragma unroll
            for (int tp = 0; tp < 4; tp++) {
                const uint32_t row = (uint32_t)(tp * 16 + b_rl);
                const uint32_t byteoff = (kb + b_khi) ^ (((row >> 3) & 3u) << 4);
                LDMATRIX_X4(bfr[tp][0], bfr[tp][1], bfr[tp][2], bfr[tp][3],
                            sV + row * 272u + byteoff);
            }
#pragma unroll
            for (int tn = 0; tn < 8; tn++)
                mma_tf32(oacc[tn], afr,
                         bfr[tn >> 1][(tn & 1) * 2 + 0],
                         bfr[tn >> 1][(tn & 1) * 2 + 1]);
        }
    }

    // ---- normalize, tf32-round (GEMM2 consumes raw), write ctx ----
#pragma unroll
    for (int hh = 0; hh < 2; hh++) {
        const float inv = 1.0f / (l1[hh] + EPS * l2[hh]);
        const int gq = q0g + q0 + (lane >> 2) + 8 * hh;
#pragma unroll
        for (int tn = 0; tn < 8; tn++) {
            const int d = tn * 8 + (lane & 3) * 2;
            float2 o;
            o.x = tf32r(oacc[tn][2 * hh + 0] * inv);
            o.y = tf32r(oacc[tn][2 * hh + 1] * inv);
            *(float2*)&g_ctx[(size_t)(b * T + gq) * D + h * DH + d] = o;
        }
    }
}

// ============================================================================
// launch
// ============================================================================
extern "C" void kernel_launch(void* const* d_in, const int* in_sizes, int n_in,
                              void* d_out, int out_size)
{
    (void)in_sizes; (void)n_in; (void)out_size;
    const float* inputs = (const float*)d_in[0];
    const float* mask   = (const float*)d_in[1];
    const float* adj    = (const float*)d_in[2];
    const float* W_qkv  = (const float*)d_in[3];
    const float* b_qkv  = (const float*)d_in[4];
    const float* W_out  = (const float*)d_in[5];
    const float* b_out  = (const float*)d_in[6];
    float* out = (float*)d_out;

    cudaFuncSetAttribute(gemm_mma_kernel<0>,
                         cudaFuncAttributeMaxDynamicSharedMemorySize,
                         GEMM_SMEM_BYTES);
    cudaFuncSetAttribute(gemm_mma_kernel<1>,
                         cudaFuncAttributeMaxDynamicSharedMemorySize,
                         GEMM_SMEM_BYTES);
    cudaFuncSetAttribute(attn_mma_kernel,
                         cudaFuncAttributeMaxDynamicSharedMemorySize,
                         ATTN_SMEM_BYTES);

    float *p_in_r, *p_wqkv_r, *p_wout_r;
    cudaGetSymbolAddress((void**)&p_in_r,   g_in_r);
    cudaGetSymbolAddress((void**)&p_wqkv_r, g_wqkv_r);
    cudaGetSymbolAddress((void**)&p_wout_r, g_wout_r);

    dim3 blk(256);

    // tf32 pre-round pass (keeps all cvts out of GEMM hot loops)
    {
        const int n4_in   = (B * T * D) / 4;
        const int n4_wqkv = (3 * D * D) / 4;
        const int n4_wout = (D * D) / 4;
        round_tf32_kernel<<<(n4_in   + 255) / 256, blk>>>((const float4*)inputs, (float4*)p_in_r,   n4_in);
        round_tf32_kernel<<<(n4_wqkv + 255) / 256, blk>>>((const float4*)W_qkv,  (float4*)p_wqkv_r, n4_wqkv);
        round_tf32_kernel<<<(n4_wout + 255) / 256, blk>>>((const float4*)W_out,  (float4*)p_wout_r, n4_wout);
    }

    // QKV projection: M=8192, N=3072, K=1024  (tf32 mma.sync, 3-stage)
    gemm_mma_kernel<0><<<dim3((3 * D) / 128, (B * T) / 128), blk, GEMM_SMEM_BYTES>>>(
        p_in_r, p_wqkv_r, b_qkv, nullptr, D, 3 * D);

    // fused attention (tf32 mma.sync, max-free softmax)
    attn_mma_kernel<<<dim3(T / AQT, H, B), blk, ATTN_SMEM_BYTES>>>(adj, mask);

    // output projection: M=8192, N=1024, K=1024  (tf32 mma.sync, 3-stage)
    gemm_mma_kernel<1><<<dim3(D / 128, (B * T) / 128), blk, GEMM_SMEM_BYTES>>>(
        nullptr, p_wout_r, b_out, out, D, D);
}

// round 7
// speedup vs baseline: 3.2440x; 1.0089x over previous
#include <cuda_runtime.h>
#include <cstdint>

// ---------------- problem constants ----------------
constexpr int B  = 8;
constexpr int T  = 1024;
constexpr int D  = 1024;
constexpr int H  = 16;
constexpr int DH = 64;
constexpr float INV_SCALE = 0.125f;   // 1/sqrt(DH)
constexpr float EPS = 1e-13f;

// ---------------- scratch (device globals: no allocation allowed) ----------------
__device__ float g_q[(size_t)B * H * T * DH];   // 32 MB
__device__ float g_k[(size_t)B * H * T * DH];   // 32 MB
__device__ float g_v[(size_t)B * H * T * DH];   // 32 MB
__device__ float g_ctx[(size_t)B * T * D];      // 32 MB, [B*T, D] row-major (tf32-rounded)
__device__ float g_in_r[(size_t)B * T * D];     // 32 MB, tf32-rounded inputs
__device__ float g_wqkv_r[(size_t)3 * D * D];   // 12 MB, tf32-rounded W_qkv
__device__ float g_wout_r[(size_t)D * D];       //  4 MB, tf32-rounded W_out

// ---------------- PTX helpers (base-arch only) ----------------
__device__ __forceinline__ uint32_t smem_u32(const void* p) {
    uint32_t a;
    asm("{ .reg .u64 t; cvta.to.shared.u64 t, %1; cvt.u32.u64 %0, t; }"
        : "=r"(a) : "l"(p));
    return a;
}

#define CP_ASYNC16(dst, src) \
    asm volatile("cp.async.cg.shared.global [%0], [%1], 16;" :: "r"(dst), "l"(src))
#define CP_ASYNC4(dst, src) \
    asm volatile("cp.async.ca.shared.global [%0], [%1], 4;" :: "r"(dst), "l"(src))
#define CP_COMMIT()  asm volatile("cp.async.commit_group;" ::: "memory")
#define CP_WAIT(n)   asm volatile("cp.async.wait_group %0;" :: "n"(n) : "memory")

#define LDMATRIX_X4(r0, r1, r2, r3, addr) \
    asm volatile("ldmatrix.sync.aligned.m8n8.x4.shared.b16 {%0,%1,%2,%3}, [%4];" \
        : "=r"(r0), "=r"(r1), "=r"(r2), "=r"(r3) : "r"(addr))

__device__ __forceinline__ uint32_t f2tf32(uint32_t x) {
    uint32_t d;
    asm("cvt.rna.tf32.f32 %0, %1;" : "=r"(d) : "r"(x));
    return d;
}
__device__ __forceinline__ float tf32r(float x) {
    return __uint_as_float(f2tf32(__float_as_uint(x)));
}

__device__ __forceinline__ void mma_tf32(float* c, const uint32_t* a,
                                         uint32_t b0, uint32_t b1) {
    asm volatile(
        "mma.sync.aligned.m16n8k8.row.col.f32.tf32.tf32.f32 "
        "{%0,%1,%2,%3}, {%4,%5,%6,%7}, {%8,%9}, {%0,%1,%2,%3};"
        : "+f"(c[0]), "+f"(c[1]), "+f"(c[2]), "+f"(c[3])
        : "r"(a[0]), "r"(a[1]), "r"(a[2]), "r"(a[3]), "r"(b0), "r"(b1));
}

// ============================================================================
// tf32 pre-round pass
// ============================================================================
__global__ void __launch_bounds__(256)
round_tf32_kernel(const float4* __restrict__ src, float4* __restrict__ dst, int n4)
{
    const int i = blockIdx.x * 256 + threadIdx.x;
    if (i < n4) {
        float4 v = src[i];
        v.x = tf32r(v.x); v.y = tf32r(v.y); v.z = tf32r(v.z); v.w = tf32r(v.w);
        dst[i] = v;
    }
}

// ============================================================================
// tf32 mma.sync GEMM, 3-stage cp.async pipeline (unchanged from R6):
//   C[m,n] = sum_k A[m,k] * W[n,k] + bias[n]
// ============================================================================
constexpr int GBK = 32;
constexpr int G_TILE  = 128 * 128;
constexpr int G_STAGE = 2 * G_TILE;
constexpr int GEMM_SMEM_BYTES = 3 * G_STAGE;    // 96 KB

__device__ __forceinline__ void load_chunk(uint32_t sA, uint32_t sB,
                                           const float* __restrict__ Ab,
                                           const float* __restrict__ Wb,
                                           int K, int k0) {
    const int tid = threadIdx.x;
#pragma unroll
    for (int it = 0; it < 4; it++) {
        const int idx = it * 256 + tid;
        const int r = idx >> 3;
        const int s = idx & 7;
        const uint32_t off = (uint32_t)r * 128u + (((uint32_t)s * 16u) ^ (((uint32_t)r & 7u) << 4));
        CP_ASYNC16(sA + off, Ab + (size_t)r * K + k0 + s * 4);
    }
#pragma unroll
    for (int it = 0; it < 4; it++) {
        const int idx = it * 256 + tid;
        const int r = idx >> 3;
        const int s = idx & 7;
        const uint32_t off = (uint32_t)r * 128u + (((uint32_t)s * 16u) ^ (((uint32_t)r & 7u) << 4));
        CP_ASYNC16(sB + off, Wb + (size_t)r * K + k0 + s * 4);
    }
}

template <int MODE>
__global__ void __launch_bounds__(256)
gemm_mma_kernel(const float* __restrict__ A, const float* __restrict__ W,
                const float* __restrict__ bias, float* __restrict__ C,
                int K, int Ntot)
{
    extern __shared__ __align__(1024) char smem[];
    const uint32_t sbase = smem_u32(smem);
    const int tid  = threadIdx.x;
    const int wid  = tid >> 5;
    const int lane = tid & 31;

    const int m0 = blockIdx.y * 128;
    const int n0 = blockIdx.x * 128;

    const float* Asrc = (MODE == 1) ? (const float*)g_ctx : A;
    const float* Ab = Asrc + (size_t)m0 * K;
    const float* Wb = W    + (size_t)n0 * K;

    uint32_t sA[3], sB[3];
#pragma unroll
    for (int s = 0; s < 3; s++) {
        sA[s] = sbase + s * G_STAGE;
        sB[s] = sA[s] + G_TILE;
    }

    const int wm = (wid >> 2) * 64;
    const int wn = (wid & 3) * 32;

    const int arow       = wm + (lane & 15);
    const uint32_t aoff  = (uint32_t)arow * 128u;
    const uint32_t aswz  = ((uint32_t)arow & 7u) << 4;
    const uint32_t akhi  = (uint32_t)(lane & 16);
    const int brow       = wn + (lane & 7) + ((lane & 16) >> 1);
    const uint32_t boff  = (uint32_t)brow * 128u;
    const uint32_t bswz  = ((uint32_t)brow & 7u) << 4;
    const uint32_t bkhi  = (uint32_t)((lane & 8) << 1);

    float acc[4][4][4];
#pragma unroll
    for (int i = 0; i < 4; i++)
#pragma unroll
        for (int j = 0; j < 4; j++)
#pragma unroll
            for (int e = 0; e < 4; e++) acc[i][j][e] = 0.f;

    const int NC = K / GBK;

    load_chunk(sA[0], sB[0], Ab, Wb, K, 0);
    CP_COMMIT();
    load_chunk(sA[1], sB[1], Ab, Wb, K, GBK);
    CP_COMMIT();

    int st = 0;
    for (int i = 0; i < NC; i++) {
        CP_WAIT(1);
        __syncthreads();

        const int pst = (st + 2 >= 3) ? st + 2 - 3 : st + 2;
        if (i + 2 < NC)
            load_chunk(sA[pst], sB[pst], Ab, Wb, K, (i + 2) * GBK);
        CP_COMMIT();

        const uint32_t aB = sA[st];
        const uint32_t bB = sB[st];

#pragma unroll
        for (int ks = 0; ks < 4; ks++) {
            const uint32_t kb = (uint32_t)ks * 32u;
            uint32_t afr[4][4];
#pragma unroll
            for (int tm = 0; tm < 4; tm++) {
                const uint32_t addr = aB + aoff + (uint32_t)tm * 2048u + ((kb + akhi) ^ aswz);
                LDMATRIX_X4(afr[tm][0], afr[tm][1], afr[tm][2], afr[tm][3], addr);
            }
            uint32_t bfr[2][4];
#pragma unroll
            for (int tp = 0; tp < 2; tp++) {
                const uint32_t addr = bB + boff + (uint32_t)tp * 2048u + ((kb + bkhi) ^ bswz);
                LDMATRIX_X4(bfr[tp][0], bfr[tp][1], bfr[tp][2], bfr[tp][3], addr);
            }
#pragma unroll
            for (int tm = 0; tm < 4; tm++)
#pragma unroll
                for (int tn = 0; tn < 4; tn++)
                    mma_tf32(acc[tm][tn], afr[tm],
                             bfr[tn >> 1][(tn & 1) * 2 + 0],
                             bfr[tn >> 1][(tn & 1) * 2 + 1]);
        }
        st = (st + 1 >= 3) ? 0 : st + 1;
    }

#pragma unroll
    for (int tm = 0; tm < 4; tm++) {
#pragma unroll
        for (int tn = 0; tn < 4; tn++) {
            const int col = n0 + wn + tn * 8 + (lane & 3) * 2;
            const float bx = bias[col], by = bias[col + 1];
#pragma unroll
            for (int half = 0; half < 2; half++) {
                const int row = m0 + wm + tm * 16 + (lane >> 2) + half * 8;
                float2 v;
                v.x = acc[tm][tn][half * 2 + 0] + bx;
                v.y = acc[tm][tn][half * 2 + 1] + by;
                if (MODE == 0) {
                    v.x = tf32r(v.x); v.y = tf32r(v.y);
                    const int sel = col >> 10;
                    float* dst = (sel == 0) ? g_q : (sel == 1) ? g_k : g_v;
                    const int bb = row >> 10;
                    const int t  = row & 1023;
                    const int hh = (col & 1023) >> 6;
                    const int d  = col & 63;
                    *(float2*)&dst[((size_t)(bb * H + hh) * T + t) * DH + d] = v;
                } else {
                    *(float2*)&C[(size_t)row * Ntot + col] = v;
                }
            }
        }
    }
}

// ============================================================================
// Fused flash attention, tf32 mma.sync, max-free softmax,
// cp.async DOUBLE-BUFFERED K/V/adj/mask (tile kt+1 streams during compute kt).
// One CP_WAIT + __syncthreads per tile. P buffer is warp-private rows.
// ============================================================================
constexpr int AQT = 128;
constexpr int AKT = 64;
constexpr int ASS = 68;                    // row stride in floats (272 B)
// float offsets
constexpr int OFF_Q  = 0;                  // [128][68]
constexpr int OFF_K0 = OFF_Q  + AQT * ASS; // [64][68]
constexpr int OFF_K1 = OFF_K0 + AKT * ASS;
constexpr int OFF_V0 = OFF_K1 + AKT * ASS; // [64][68] transposed chunk-XOR
constexpr int OFF_V1 = OFF_V0 + AKT * ASS;
constexpr int OFF_A0 = OFF_V1 + AKT * ASS; // [128][68]
constexpr int OFF_A1 = OFF_A0 + AQT * ASS;
constexpr int OFF_P  = OFF_A1 + AQT * ASS; // [128][68]
constexpr int OFF_M0 = OFF_P  + AQT * ASS; // [64]
constexpr int OFF_M1 = OFF_M0 + AKT;
constexpr int ATTN_SMEM_BYTES = (OFF_M1 + AKT) * 4;   // 209,920 B

__device__ __forceinline__ void attn_load_tile(
    uint32_t sKb, uint32_t sVb, uint32_t sAb, uint32_t sMb,
    const float* __restrict__ kbase, const float* __restrict__ vbase,
    const float* __restrict__ aptr,  const float* __restrict__ mrow,
    int kk0, int tid)
{
    // K: 64 x 64 floats -> [64][68] row-major, 16B chunks
#pragma unroll
    for (int it = 0; it < 4; it++) {
        const int idx = it * 256 + tid;
        const int r = idx >> 4, s = idx & 15;
        CP_ASYNC16(sKb + (uint32_t)r * 272u + (uint32_t)s * 16u,
                   kbase + (size_t)(kk0 + r) * DH + s * 4);
    }
    // V transposed: element (c,d) -> VT[d][c] with chunk-XOR; 4B copies
#pragma unroll
    for (int it = 0; it < 16; it++) {
        const int idx = it * 256 + tid;
        const int c = idx >> 6;
        const int d = idx & 63;
        const uint32_t byte = (uint32_t)d * 272u +
                              (((uint32_t)c * 4u) ^ ((((uint32_t)d >> 3) & 3u) << 4));
        CP_ASYNC4(sVb + byte, vbase + (size_t)(kk0 + c) * DH + d);
    }
    // adj: 128 x 64 floats -> [128][68]
#pragma unroll
    for (int it = 0; it < 8; it++) {
        const int idx = it * 256 + tid;
        const int r = idx >> 4, s = idx & 15;
        CP_ASYNC16(sAb + (uint32_t)r * 272u + (uint32_t)s * 16u,
                   aptr + (size_t)r * T + kk0 + s * 4);
    }
    // mask chunk: 64 floats
    if (tid < 16)
        CP_ASYNC16(sMb + (uint32_t)tid * 16u, mrow + kk0 + tid * 4);
}

__global__ void __launch_bounds__(256, 1)
attn_mma_kernel(const float* __restrict__ adj, const float* __restrict__ mask)
{
    extern __shared__ __align__(16) float sh[];

    const int b   = blockIdx.z;
    const int h   = blockIdx.y;
    const int q0g = blockIdx.x * AQT;
    const int tid = threadIdx.x;
    const int wid = tid >> 5;
    const int lane = tid & 31;
    const int q0  = wid * 16;

    const float* qptr  = g_q + ((size_t)(b * H + h) * T + q0g) * DH;
    const float* kbase = g_k + (size_t)(b * H + h) * T * DH;
    const float* vbase = g_v + (size_t)(b * H + h) * T * DH;
    const float* aptr  = adj + ((size_t)b * T + q0g) * T;
    const float* mrow  = mask + (size_t)b * T;

    const uint32_t sbase = smem_u32(sh);
    const uint32_t sQ = sbase + OFF_Q * 4;
    const uint32_t sK[2] = { sbase + OFF_K0 * 4, sbase + OFF_K1 * 4 };
    const uint32_t sV[2] = { sbase + OFF_V0 * 4, sbase + OFF_V1 * 4 };
    const uint32_t sA[2] = { sbase + OFF_A0 * 4, sbase + OFF_A1 * 4 };
    const uint32_t sM[2] = { sbase + OFF_M0 * 4, sbase + OFF_M1 * 4 };
    const uint32_t sP = sbase + OFF_P * 4;
    float* Ps = sh + OFF_P;

    // ---- load Q once: scale by exact power of two (stays tf32) ----
#pragma unroll
    for (int it = 0; it < 8; it++) {
        const int idx = it * 256 + tid;
        const int r = idx >> 4, s = idx & 15;
        float4 v = *(const float4*)(qptr + (size_t)r * DH + s * 4);
        v.x *= INV_SCALE; v.y *= INV_SCALE; v.z *= INV_SCALE; v.w *= INV_SCALE;
        *(float4*)(sh + OFF_Q + r * ASS + s * 4) = v;
    }

    // fragment lane addressing (verified mapping)
    const uint32_t a_row_off = (uint32_t)(q0 + (lane & 15)) * 272u;
    const uint32_t a_khi     = (uint32_t)(lane & 16);
    const int      b_rl      = (lane & 7) + ((lane & 16) >> 1);
    const uint32_t b_khi     = (uint32_t)((lane & 8) << 1);

    float oacc[8][4];
#pragma unroll
    for (int tn = 0; tn < 8; tn++)
#pragma unroll
        for (int e = 0; e < 4; e++) oacc[tn][e] = 0.f;
    float l1[2] = { 0.f, 0.f };
    float l2[2] = { 0.f, 0.f };

    constexpr int NT = T / AKT;

    // prologue: prefetch tile 0 into buffer 0
    attn_load_tile(sK[0], sV[0], sA[0], sM[0], kbase, vbase, aptr, mrow, 0, tid);
    CP_COMMIT();

    for (int kt = 0; kt < NT; kt++) {
        const int cur = kt & 1;

        CP_WAIT(0);          // tile kt resident
        __syncthreads();     // visible to all; compute(kt-1) done by all

        if (kt + 1 < NT) {
            attn_load_tile(sK[1 - cur], sV[1 - cur], sA[1 - cur], sM[1 - cur],
                           kbase, vbase, aptr, mrow, (kt + 1) * AKT, tid);
        }
        CP_COMMIT();

        const uint32_t sKb = sK[cur];
        const uint32_t sVb = sV[cur];
        const float* As = sh + (cur ? OFF_A1 : OFF_A0);
        const float* Ms = sh + (cur ? OFF_M1 : OFF_M0);

        // ---- S = Q @ K^T ----
        float sacc[8][4];
#pragma unroll
        for (int tn = 0; tn < 8; tn++)
#pragma unroll
            for (int e = 0; e < 4; e++) sacc[tn][e] = 0.f;

#pragma unroll
        for (int ks = 0; ks < 8; ks++) {
            const uint32_t kb = (uint32_t)ks * 32u;
            uint32_t afr[4];
            LDMATRIX_X4(afr[0], afr[1], afr[2], afr[3], sQ + a_row_off + kb + a_khi);
            uint32_t bfr[4][4];
#pragma unroll
            for (int tp = 0; tp < 4; tp++) {
                const uint32_t addr = sKb + (uint32_t)(tp * 16 + b_rl) * 272u + kb + b_khi;
                LDMATRIX_X4(bfr[tp][0], bfr[tp][1], bfr[tp][2], bfr[tp][3], addr);
            }
#pragma unroll
            for (int tn = 0; tn < 8; tn++)
                mma_tf32(sacc[tn], afr,
                         bfr[tn >> 1][(tn & 1) * 2 + 0],
                         bfr[tn >> 1][(tn & 1) * 2 + 1]);
        }

        // ---- max-free softmax: p = exp(s*adj*m), P -> Ps (tf32), sums ----
#pragma unroll
        for (int hh = 0; hh < 2; hh++) {
            const int rq = q0 + (lane >> 2) + 8 * hh;
            float s1s = 0.f, s2s = 0.f;
#pragma unroll
            for (int tn = 0; tn < 8; tn++) {
                const int cc = tn * 8 + (lane & 3) * 2;
                const float2 a2 = *(const float2*)&As[rq * ASS + cc];
                const float2 m2 = *(const float2*)&Ms[cc];
                const float p0 = __expf(sacc[tn][2 * hh + 0] * a2.x * m2.x);
                const float p1 = __expf(sacc[tn][2 * hh + 1] * a2.y * m2.y);
                const float pm0 = p0 * m2.x;
                const float pm1 = p1 * m2.y;
                s2s += p0 + p1;
                s1s += pm0 + pm1;
                float2 pw;
                pw.x = tf32r(pm0);
                pw.y = tf32r(pm1);
                *(float2*)&Ps[rq * ASS + cc] = pw;
            }
            s1s += __shfl_xor_sync(0xffffffffu, s1s, 1);
            s1s += __shfl_xor_sync(0xffffffffu, s1s, 2);
            s2s += __shfl_xor_sync(0xffffffffu, s2s, 1);
            s2s += __shfl_xor_sync(0xffffffffu, s2s, 2);
            l1[hh] += s1s; l2[hh] += s2s;
        }
        __syncwarp();   // P stores visible to this warp's ldmatrix

        // ---- O += P @ V ----
#pragma unroll
        for (int cs = 0; cs < 8; cs++) {
            const uint32_t kb = (uint32_t)cs * 32u;
            uint32_t afr[4];
            LDMATRIX_X4(afr[0], afr[1], afr[2], afr[3], sP + a_row_off + kb + a_khi);
            uint32_t bfr[4][4];
#pragma unroll
            for (int tp = 0; tp < 4; tp++) {
                const uint32_t row = (uint32_t)(tp * 16 + b_rl);
                const uint32_t byteoff = (kb + b_khi) ^ (((row >> 3) & 3u) << 4);
                LDMATRIX_X4(bfr[tp][0], bfr[tp][1], bfr[tp][2], bfr[tp][3],
                            sVb + row * 272u + byteoff);
            }
#pragma unroll
            for (int tn = 0; tn < 8; tn++)
                mma_tf32(oacc[tn], afr,
                         bfr[tn >> 1][(tn & 1) * 2 + 0],
                         bfr[tn >> 1][(tn & 1) * 2 + 1]);
        }
    }

    // ---- normalize, tf32-round (GEMM2 consumes raw), write ctx ----
#pragma unroll
    for (int hh = 0; hh < 2; hh++) {
        const float inv = 1.0f / (l1[hh] + EPS * l2[hh]);
        const int gq = q0g + q0 + (lane >> 2) + 8 * hh;
#pragma unroll
        for (int tn = 0; tn < 8; tn++) {
            const int d = tn * 8 + (lane & 3) * 2;
            float2 o;
            o.x = tf32r(oacc[tn][2 * hh + 0] * inv);
            o.y = tf32r(oacc[tn][2 * hh + 1] * inv);
            *(float2*)&g_ctx[(size_t)(b * T + gq) * D + h * DH + d] = o;
        }
    }
}

// ============================================================================
// launch
// ============================================================================
extern "C" void kernel_launch(void* const* d_in, const int* in_sizes, int n_in,
                              void* d_out, int out_size)
{
    (void)in_sizes; (void)n_in; (void)out_size;
    const float* inputs = (const float*)d_in[0];
    const float* mask   = (const float*)d_in[1];
    const float* adj    = (const float*)d_in[2];
    const float* W_qkv  = (const float*)d_in[3];
    const float* b_qkv  = (const float*)d_in[4];
    const float* W_out  = (const float*)d_in[5];
    const float* b_out  = (const float*)d_in[6];
    float* out = (float*)d_out;

    cudaFuncSetAttribute(gemm_mma_kernel<0>,
                         cudaFuncAttributeMaxDynamicSharedMemorySize,
                         GEMM_SMEM_BYTES);
    cudaFuncSetAttribute(gemm_mma_kernel<1>,
                         cudaFuncAttributeMaxDynamicSharedMemorySize,
                         GEMM_SMEM_BYTES);
    cudaFuncSetAttribute(attn_mma_kernel,
                         cudaFuncAttributeMaxDynamicSharedMemorySize,
                         ATTN_SMEM_BYTES);

    float *p_in_r, *p_wqkv_r, *p_wout_r;
    cudaGetSymbolAddress((void**)&p_in_r,   g_in_r);
    cudaGetSymbolAddress((void**)&p_wqkv_r, g_wqkv_r);
    cudaGetSymbolAddress((void**)&p_wout_r, g_wout_r);

    dim3 blk(256);

    // tf32 pre-round pass
    {
        const int n4_in   = (B * T * D) / 4;
        const int n4_wqkv = (3 * D * D) / 4;
        const int n4_wout = (D * D) / 4;
        round_tf32_kernel<<<(n4_in   + 255) / 256, blk>>>((const float4*)inputs, (float4*)p_in_r,   n4_in);
        round_tf32_kernel<<<(n4_wqkv + 255) / 256, blk>>>((const float4*)W_qkv,  (float4*)p_wqkv_r, n4_wqkv);
        round_tf32_kernel<<<(n4_wout + 255) / 256, blk>>>((const float4*)W_out,  (float4*)p_wout_r, n4_wout);
    }

    // QKV projection (tf32 mma.sync, 3-stage)
    gemm_mma_kernel<0><<<dim3((3 * D) / 128, (B * T) / 128), blk, GEMM_SMEM_BYTES>>>(
        p_in_r, p_wqkv_r, b_qkv, nullptr, D, 3 * D);

    // fused attention (tf32 mma.sync, cp.async double-buffered tiles)
    attn_mma_kernel<<<dim3(T / AQT, H, B), blk, ATTN_SMEM_BYTES>>>(adj, mask);

    // output projection (tf32 mma.sync, 3-stage)
    gemm_mma_kernel<1><<<dim3(D / 128, (B * T) / 128), blk, GEMM_SMEM_BYTES>>>(
        nullptr, p_wout_r, b_out, out, D, D);
}

// round 8
// speedup vs baseline: 3.2967x; 1.0163x over previous
#include <cuda_runtime.h>
#include <cstdint>

// ---------------- problem constants ----------------
constexpr int B  = 8;
constexpr int T  = 1024;
constexpr int D  = 1024;
constexpr int H  = 16;
constexpr int DH = 64;
constexpr float INV_SCALE = 0.125f;   // 1/sqrt(DH)
constexpr float EPS = 1e-13f;

// ---------------- scratch (device globals: no allocation allowed) ----------------
__device__ float g_q[(size_t)B * H * T * DH];
__device__ float g_k[(size_t)B * H * T * DH];
__device__ float g_v[(size_t)B * H * T * DH];
__device__ float g_ctx[(size_t)B * T * D];
__device__ float g_in_r[(size_t)B * T * D];
__device__ float g_wqkv_r[(size_t)3 * D * D];
__device__ float g_wout_r[(size_t)D * D];

// ---------------- PTX helpers (base-arch only) ----------------
__device__ __forceinline__ uint32_t smem_u32(const void* p) {
    uint32_t a;
    asm("{ .reg .u64 t; cvta.to.shared.u64 t, %1; cvt.u32.u64 %0, t; }"
        : "=r"(a) : "l"(p));
    return a;
}

#define CP_ASYNC16(dst, src) \
    asm volatile("cp.async.cg.shared.global [%0], [%1], 16;" :: "r"(dst), "l"(src))
#define CP_ASYNC4(dst, src) \
    asm volatile("cp.async.ca.shared.global [%0], [%1], 4;" :: "r"(dst), "l"(src))
#define CP_COMMIT()  asm volatile("cp.async.commit_group;" ::: "memory")
#define CP_WAIT(n)   asm volatile("cp.async.wait_group %0;" :: "n"(n) : "memory")

#define LDMATRIX_X4(r0, r1, r2, r3, addr) \
    asm volatile("ldmatrix.sync.aligned.m8n8.x4.shared.b16 {%0,%1,%2,%3}, [%4];" \
        : "=r"(r0), "=r"(r1), "=r"(r2), "=r"(r3) : "r"(addr))

__device__ __forceinline__ uint32_t f2tf32(uint32_t x) {
    uint32_t d;
    asm("cvt.rna.tf32.f32 %0, %1;" : "=r"(d) : "r"(x));
    return d;
}
__device__ __forceinline__ float tf32r(float x) {
    return __uint_as_float(f2tf32(__float_as_uint(x)));
}

__device__ __forceinline__ void mma_tf32(float* c, const uint32_t* a,
                                         uint32_t b0, uint32_t b1) {
    asm volatile(
        "mma.sync.aligned.m16n8k8.row.col.f32.tf32.tf32.f32 "
        "{%0,%1,%2,%3}, {%4,%5,%6,%7}, {%8,%9}, {%0,%1,%2,%3};"
        : "+f"(c[0]), "+f"(c[1]), "+f"(c[2]), "+f"(c[3])
        : "r"(a[0]), "r"(a[1]), "r"(a[2]), "r"(a[3]), "r"(b0), "r"(b1));
}

// ============================================================================
// tf32 pre-round pass
// ============================================================================
__global__ void __launch_bounds__(256)
round_tf32_kernel(const float4* __restrict__ src, float4* __restrict__ dst, int n4)
{
    const int i = blockIdx.x * 256 + threadIdx.x;
    if (i < n4) {
        float4 v = src[i];
        v.x = tf32r(v.x); v.y = tf32r(v.y); v.z = tf32r(v.z); v.w = tf32r(v.w);
        dst[i] = v;
    }
}

// ============================================================================
// tf32 mma.sync GEMM, 3-stage cp.async pipeline + register fragment pipelining
// ============================================================================
constexpr int GBK = 32;
constexpr int G_TILE  = 128 * 128;
constexpr int G_STAGE = 2 * G_TILE;
constexpr int GEMM_SMEM_BYTES = 3 * G_STAGE;    // 96 KB

__device__ __forceinline__ void load_chunk(uint32_t sA, uint32_t sB,
                                           const float* __restrict__ Ab,
                                           const float* __restrict__ Wb,
                                           int K, int k0) {
    const int tid = threadIdx.x;
#pragma unroll
    for (int it = 0; it < 4; it++) {
        const int idx = it * 256 + tid;
        const int r = idx >> 3;
        const int s = idx & 7;
        const uint32_t off = (uint32_t)r * 128u + (((uint32_t)s * 16u) ^ (((uint32_t)r & 7u) << 4));
        CP_ASYNC16(sA + off, Ab + (size_t)r * K + k0 + s * 4);
    }
#pragma unroll
    for (int it = 0; it < 4; it++) {
        const int idx = it * 256 + tid;
        const int r = idx >> 3;
        const int s = idx & 7;
        const uint32_t off = (uint32_t)r * 128u + (((uint32_t)s * 16u) ^ (((uint32_t)r & 7u) << 4));
        CP_ASYNC16(sB + off, Wb + (size_t)r * K + k0 + s * 4);
    }
}

template <int MODE>
__global__ void __launch_bounds__(256, 2)
gemm_mma_kernel(const float* __restrict__ A, const float* __restrict__ W,
                const float* __restrict__ bias, float* __restrict__ C,
                int K, int Ntot)
{
    extern __shared__ __align__(1024) char smem[];
    const uint32_t sbase = smem_u32(smem);
    const int tid  = threadIdx.x;
    const int wid  = tid >> 5;
    const int lane = tid & 31;

    const int m0 = blockIdx.y * 128;
    const int n0 = blockIdx.x * 128;

    const float* Asrc = (MODE == 1) ? (const float*)g_ctx : A;
    const float* Ab = Asrc + (size_t)m0 * K;
    const float* Wb = W    + (size_t)n0 * K;

    uint32_t sA[3], sB[3];
#pragma unroll
    for (int s = 0; s < 3; s++) {
        sA[s] = sbase + s * G_STAGE;
        sB[s] = sA[s] + G_TILE;
    }

    const int wm = (wid >> 2) * 64;
    const int wn = (wid & 3) * 32;

    const int arow       = wm + (lane & 15);
    const uint32_t aoff  = (uint32_t)arow * 128u;
    const uint32_t aswz  = ((uint32_t)arow & 7u) << 4;
    const uint32_t akhi  = (uint32_t)(lane & 16);
    const int brow       = wn + (lane & 7) + ((lane & 16) >> 1);
    const uint32_t boff  = (uint32_t)brow * 128u;
    const uint32_t bswz  = ((uint32_t)brow & 7u) << 4;
    const uint32_t bkhi  = (uint32_t)((lane & 8) << 1);

    float acc[4][4][4];
#pragma unroll
    for (int i = 0; i < 4; i++)
#pragma unroll
        for (int j = 0; j < 4; j++)
#pragma unroll
            for (int e = 0; e < 4; e++) acc[i][j][e] = 0.f;

    const int NC = K / GBK;

    load_chunk(sA[0], sB[0], Ab, Wb, K, 0);
    CP_COMMIT();
    load_chunk(sA[1], sB[1], Ab, Wb, K, GBK);
    CP_COMMIT();

    uint32_t afr[2][4][4], bfr[2][2][4];

    int st = 0;
    for (int i = 0; i < NC; i++) {
        CP_WAIT(1);
        __syncthreads();

        const int pst = (st + 2 >= 3) ? st + 2 - 3 : st + 2;
        if (i + 2 < NC)
            load_chunk(sA[pst], sB[pst], Ab, Wb, K, (i + 2) * GBK);
        CP_COMMIT();

        const uint32_t aB = sA[st];
        const uint32_t bB = sB[st];

        // ks=0 fragments into buffer 0
#pragma unroll
        for (int tm = 0; tm < 4; tm++) {
            const uint32_t addr = aB + aoff + (uint32_t)tm * 2048u + (akhi ^ aswz);
            LDMATRIX_X4(afr[0][tm][0], afr[0][tm][1], afr[0][tm][2], afr[0][tm][3], addr);
        }
#pragma unroll
        for (int tp = 0; tp < 2; tp++) {
            const uint32_t addr = bB + boff + (uint32_t)tp * 2048u + (bkhi ^ bswz);
            LDMATRIX_X4(bfr[0][tp][0], bfr[0][tp][1], bfr[0][tp][2], bfr[0][tp][3], addr);
        }

#pragma unroll
        for (int ks = 0; ks < 4; ks++) {
            const int cb = ks & 1;
            if (ks < 3) {
                const int nb = cb ^ 1;
                const uint32_t kb = (uint32_t)(ks + 1) * 32u;
#pragma unroll
                for (int tm = 0; tm < 4; tm++) {
                    const uint32_t addr = aB + aoff + (uint32_t)tm * 2048u + ((kb + akhi) ^ aswz);
                    LDMATRIX_X4(afr[nb][tm][0], afr[nb][tm][1], afr[nb][tm][2], afr[nb][tm][3], addr);
                }
#pragma unroll
                for (int tp = 0; tp < 2; tp++) {
                    const uint32_t addr = bB + boff + (uint32_t)tp * 2048u + ((kb + bkhi) ^ bswz);
                    LDMATRIX_X4(bfr[nb][tp][0], bfr[nb][tp][1], bfr[nb][tp][2], bfr[nb][tp][3], addr);
                }
            }
#pragma unroll
            for (int tm = 0; tm < 4; tm++)
#pragma unroll
                for (int tn = 0; tn < 4; tn++)
                    mma_tf32(acc[tm][tn], afr[cb][tm],
                             bfr[cb][tn >> 1][(tn & 1) * 2 + 0],
                             bfr[cb][tn >> 1][(tn & 1) * 2 + 1]);
        }
        st = (st + 1 >= 3) ? 0 : st + 1;
    }

#pragma unroll
    for (int tm = 0; tm < 4; tm++) {
#pragma unroll
        for (int tn = 0; tn < 4; tn++) {
            const int col = n0 + wn + tn * 8 + (lane & 3) * 2;
            const float bx = bias[col], by = bias[col + 1];
#pragma unroll
            for (int half = 0; half < 2; half++) {
                const int row = m0 + wm + tm * 16 + (lane >> 2) + half * 8;
                float2 v;
                v.x = acc[tm][tn][half * 2 + 0] + bx;
                v.y = acc[tm][tn][half * 2 + 1] + by;
                if (MODE == 0) {
                    v.x = tf32r(v.x); v.y = tf32r(v.y);
                    const int sel = col >> 10;
                    float* dst = (sel == 0) ? g_q : (sel == 1) ? g_k : g_v;
                    const int bb = row >> 10;
                    const int t  = row & 1023;
                    const int hh = (col & 1023) >> 6;
                    const int d  = col & 63;
                    *(float2*)&dst[((size_t)(bb * H + hh) * T + t) * DH + d] = v;
                } else {
                    *(float2*)&C[(size_t)row * Ntot + col] = v;
                }
            }
        }
    }
}

// ============================================================================
// Fused flash attention, tf32 mma.sync, max-free softmax, cp.async
// double-buffered tiles, Q fragments hoisted, K/V fragments pipelined.
// ============================================================================
constexpr int AQT = 128;
constexpr int AKT = 64;
constexpr int ASS = 68;
constexpr int OFF_Q  = 0;
constexpr int OFF_K0 = OFF_Q  + AQT * ASS;
constexpr int OFF_K1 = OFF_K0 + AKT * ASS;
constexpr int OFF_V0 = OFF_K1 + AKT * ASS;
constexpr int OFF_V1 = OFF_V0 + AKT * ASS;
constexpr int OFF_A0 = OFF_V1 + AKT * ASS;
constexpr int OFF_A1 = OFF_A0 + AQT * ASS;
constexpr int OFF_P  = OFF_A1 + AQT * ASS;
constexpr int OFF_M0 = OFF_P  + AQT * ASS;
constexpr int OFF_M1 = OFF_M0 + AKT;
constexpr int ATTN_SMEM_BYTES = (OFF_M1 + AKT) * 4;   // 209,920 B

__device__ __forceinline__ void attn_load_tile(
    uint32_t sKb, uint32_t sVb, uint32_t sAb, uint32_t sMb,
    const float* __restrict__ kbase, const float* __restrict__ vbase,
    const float* __restrict__ aptr,  const float* __restrict__ mrow,
    int kk0, int tid)
{
#pragma unroll
    for (int it = 0; it < 4; it++) {
        const int idx = it * 256 + tid;
        const int r = idx >> 4, s = idx & 15;
        CP_ASYNC16(sKb + (uint32_t)r * 272u + (uint32_t)s * 16u,
                   kbase + (size_t)(kk0 + r) * DH + s * 4);
    }
#pragma unroll
    for (int it = 0; it < 16; it++) {
        const int idx = it * 256 + tid;
        const int c = idx >> 6;
        const int d = idx & 63;
        const uint32_t byte = (uint32_t)d * 272u +
                              (((uint32_t)c * 4u) ^ ((((uint32_t)d >> 3) & 3u) << 4));
        CP_ASYNC4(sVb + byte, vbase + (size_t)(kk0 + c) * DH + d);
    }
#pragma unroll
    for (int it = 0; it < 8; it++) {
        const int idx = it * 256 + tid;
        const int r = idx >> 4, s = idx & 15;
        CP_ASYNC16(sAb + (uint32_t)r * 272u + (uint32_t)s * 16u,
                   aptr + (size_t)r * T + kk0 + s * 4);
    }
    if (tid < 16)
        CP_ASYNC16(sMb + (uint32_t)tid * 16u, mrow + kk0 + tid * 4);
}

__global__ void __launch_bounds__(256, 1)
attn_mma_kernel(const float* __restrict__ adj, const float* __restrict__ mask)
{
    extern __shared__ __align__(16) float sh[];

    const int b   = blockIdx.z;
    const int h   = blockIdx.y;
    const int q0g = blockIdx.x * AQT;
    const int tid = threadIdx.x;
    const int wid = tid >> 5;
    const int lane = tid & 31;
    const int q0  = wid * 16;

    const float* qptr  = g_q + ((size_t)(b * H + h) * T + q0g) * DH;
    const float* kbase = g_k + (size_t)(b * H + h) * T * DH;
    const float* vbase = g_v + (size_t)(b * H + h) * T * DH;
    const float* aptr  = adj + ((size_t)b * T + q0g) * T;
    const float* mrow  = mask + (size_t)b * T;

    const uint32_t sbase = smem_u32(sh);
    const uint32_t sQ = sbase + OFF_Q * 4;
    const uint32_t sK[2] = { sbase + OFF_K0 * 4, sbase + OFF_K1 * 4 };
    const uint32_t sV[2] = { sbase + OFF_V0 * 4, sbase + OFF_V1 * 4 };
    const uint32_t sP = sbase + OFF_P * 4;
    float* Ps = sh + OFF_P;

    // ---- load Q once: scale by exact power of two (stays tf32) ----
#pragma unroll
    for (int it = 0; it < 8; it++) {
        const int idx = it * 256 + tid;
        const int r = idx >> 4, s = idx & 15;
        float4 v = *(const float4*)(qptr + (size_t)r * DH + s * 4);
        v.x *= INV_SCALE; v.y *= INV_SCALE; v.z *= INV_SCALE; v.w *= INV_SCALE;
        *(float4*)(sh + OFF_Q + r * ASS + s * 4) = v;
    }

    // prefetch tile 0 while Q stores drain
    attn_load_tile(sK[0], sV[0], sbase + OFF_A0 * 4, sbase + OFF_M0 * 4,
                   kbase, vbase, aptr, mrow, 0, tid);
    CP_COMMIT();

    const uint32_t a_row_off = (uint32_t)(q0 + (lane & 15)) * 272u;
    const uint32_t a_khi     = (uint32_t)(lane & 16);
    const int      b_rl      = (lane & 7) + ((lane & 16) >> 1);
    const uint32_t b_khi     = (uint32_t)((lane & 8) << 1);

    __syncthreads();   // Q stores visible to all warps

    // ---- hoist Q fragments to registers (loop-invariant) ----
    uint32_t qfr[8][4];
#pragma unroll
    for (int ks = 0; ks < 8; ks++) {
        LDMATRIX_X4(qfr[ks][0], qfr[ks][1], qfr[ks][2], qfr[ks][3],
                    sQ + a_row_off + (uint32_t)ks * 32u + a_khi);
    }

    float oacc[8][4];
#pragma unroll
    for (int tn = 0; tn < 8; tn++)
#pragma unroll
        for (int e = 0; e < 4; e++) oacc[tn][e] = 0.f;
    float l1[2] = { 0.f, 0.f };
    float l2[2] = { 0.f, 0.f };

    constexpr int NT = T / AKT;
    uint32_t bfr[2][4][4];

    for (int kt = 0; kt < NT; kt++) {
        const int cur = kt & 1;

        CP_WAIT(0);
        __syncthreads();

        if (kt + 1 < NT) {
            attn_load_tile(sK[1 - cur], sV[1 - cur],
                           sbase + (cur ? OFF_A0 : OFF_A1) * 4,
                           sbase + (cur ? OFF_M0 : OFF_M1) * 4,
                           kbase, vbase, aptr, mrow, (kt + 1) * AKT, tid);
        }
        CP_COMMIT();

        const uint32_t sKb = sK[cur];
        const uint32_t sVb = sV[cur];
        const float* As = sh + (cur ? OFF_A1 : OFF_A0);
        const float* Ms = sh + (cur ? OFF_M1 : OFF_M0);

        // ---- S = Q @ K^T, K fragments register-pipelined ----
        float sacc[8][4];
#pragma unroll
        for (int tn = 0; tn < 8; tn++)
#pragma unroll
            for (int e = 0; e < 4; e++) sacc[tn][e] = 0.f;

#pragma unroll
        for (int tp = 0; tp < 4; tp++) {
            const uint32_t addr = sKb + (uint32_t)(tp * 16 + b_rl) * 272u + b_khi;
            LDMATRIX_X4(bfr[0][tp][0], bfr[0][tp][1], bfr[0][tp][2], bfr[0][tp][3], addr);
        }
#pragma unroll
        for (int ks = 0; ks < 8; ks++) {
            const int cb = ks & 1;
            if (ks < 7) {
                const int nb = cb ^ 1;
                const uint32_t kb = (uint32_t)(ks + 1) * 32u;
#pragma unroll
                for (int tp = 0; tp < 4; tp++) {
                    const uint32_t addr = sKb + (uint32_t)(tp * 16 + b_rl) * 272u + kb + b_khi;
                    LDMATRIX_X4(bfr[nb][tp][0], bfr[nb][tp][1], bfr[nb][tp][2], bfr[nb][tp][3], addr);
                }
            }
#pragma unroll
            for (int tn = 0; tn < 8; tn++)
                mma_tf32(sacc[tn], qfr[ks],
                         bfr[cb][tn >> 1][(tn & 1) * 2 + 0],
                         bfr[cb][tn >> 1][(tn & 1) * 2 + 1]);
        }

        // ---- max-free softmax ----
#pragma unroll
        for (int hh = 0; hh < 2; hh++) {
            const int rq = q0 + (lane >> 2) + 8 * hh;
            float s1s = 0.f, s2s = 0.f;
#pragma unroll
            for (int tn = 0; tn < 8; tn++) {
                const int cc = tn * 8 + (lane & 3) * 2;
                const float2 a2 = *(const float2*)&As[rq * ASS + cc];
                const float2 m2 = *(const float2*)&Ms[cc];
                const float p0 = __expf(sacc[tn][2 * hh + 0] * a2.x * m2.x);
                const float p1 = __expf(sacc[tn][2 * hh + 1] * a2.y * m2.y);
                const float pm0 = p0 * m2.x;
                const float pm1 = p1 * m2.y;
                s2s += p0 + p1;
                s1s += pm0 + pm1;
                float2 pw;
                pw.x = tf32r(pm0);
                pw.y = tf32r(pm1);
                *(float2*)&Ps[rq * ASS + cc] = pw;
            }
            s1s += __shfl_xor_sync(0xffffffffu, s1s, 1);
            s1s += __shfl_xor_sync(0xffffffffu, s1s, 2);
            s2s += __shfl_xor_sync(0xffffffffu, s2s, 1);
            s2s += __shfl_xor_sync(0xffffffffu, s2s, 2);
            l1[hh] += s1s; l2[hh] += s2s;
        }
        __syncwarp();

        // ---- O += P @ V, V fragments register-pipelined ----
#pragma unroll
        for (int tp = 0; tp < 4; tp++) {
            const uint32_t row = (uint32_t)(tp * 16 + b_rl);
            const uint32_t byteoff = b_khi ^ (((row >> 3) & 3u) << 4);
            LDMATRIX_X4(bfr[0][tp][0], bfr[0][tp][1], bfr[0][tp][2], bfr[0][tp][3],
                        sVb + row * 272u + byteoff);
        }
#pragma unroll
        for (int cs = 0; cs < 8; cs++) {
            const int cb = cs & 1;
            const uint32_t kb = (uint32_t)cs * 32u;
            uint32_t afr[4];
            LDMATRIX_X4(afr[0], afr[1], afr[2], afr[3], sP + a_row_off + kb + a_khi);
            if (cs < 7) {
                const int nb = cb ^ 1;
                const uint32_t kb2 = (uint32_t)(cs + 1) * 32u;
#pragma unroll
                for (int tp = 0; tp < 4; tp++) {
                    const uint32_t row = (uint32_t)(tp * 16 + b_rl);
                    const uint32_t byteoff = (kb2 + b_khi) ^ (((row >> 3) & 3u) << 4);
                    LDMATRIX_X4(bfr[nb][tp][0], bfr[nb][tp][1], bfr[nb][tp][2], bfr[nb][tp][3],
                                sVb + row * 272u + byteoff);
                }
            }
#pragma unroll
            for (int tn = 0; tn < 8; tn++)
                mma_tf32(oacc[tn], afr,
                         bfr[cb][tn >> 1][(tn & 1) * 2 + 0],
                         bfr[cb][tn >> 1][(tn & 1) * 2 + 1]);
        }
    }

    // ---- normalize, tf32-round, write ctx ----
#pragma unroll
    for (int hh = 0; hh < 2; hh++) {
        const float inv = 1.0f / (l1[hh] + EPS * l2[hh]);
        const int gq = q0g + q0 + (lane >> 2) + 8 * hh;
#pragma unroll
        for (int tn = 0; tn < 8; tn++) {
            const int d = tn * 8 + (lane & 3) * 2;
            float2 o;
            o.x = tf32r(oacc[tn][2 * hh + 0] * inv);
            o.y = tf32r(oacc[tn][2 * hh + 1] * inv);
            *(float2*)&g_ctx[(size_t)(b * T + gq) * D + h * DH + d] = o;
        }
    }
}

// ============================================================================
// launch
// ============================================================================
extern "C" void kernel_launch(void* const* d_in, const int* in_sizes, int n_in,
                              void* d_out, int out_size)
{
    (void)in_sizes; (void)n_in; (void)out_size;
    const float* inputs = (const float*)d_in[0];
    const float* mask   = (const float*)d_in[1];
    const float* adj    = (const float*)d_in[2];
    const float* W_qkv  = (const float*)d_in[3];
    const float* b_qkv  = (const float*)d_in[4];
    const float* W_out  = (const float*)d_in[5];
    const float* b_out  = (const float*)d_in[6];
    float* out = (float*)d_out;

    cudaFuncSetAttribute(gemm_mma_kernel<0>,
                         cudaFuncAttributeMaxDynamicSharedMemorySize,
                         GEMM_SMEM_BYTES);
    cudaFuncSetAttribute(gemm_mma_kernel<1>,
                         cudaFuncAttributeMaxDynamicSharedMemorySize,
                         GEMM_SMEM_BYTES);
    cudaFuncSetAttribute(attn_mma_kernel,
                         cudaFuncAttributeMaxDynamicSharedMemorySize,
                         ATTN_SMEM_BYTES);

    float *p_in_r, *p_wqkv_r, *p_wout_r;
    cudaGetSymbolAddress((void**)&p_in_r,   g_in_r);
    cudaGetSymbolAddress((void**)&p_wqkv_r, g_wqkv_r);
    cudaGetSymbolAddress((void**)&p_wout_r, g_wout_r);

    dim3 blk(256);

    {
        const int n4_in   = (B * T * D) / 4;
        const int n4_wqkv = (3 * D * D) / 4;
        const int n4_wout = (D * D) / 4;
        round_tf32_kernel<<<(n4_in   + 255) / 256, blk>>>((const float4*)inputs, (float4*)p_in_r,   n4_in);
        round_tf32_kernel<<<(n4_wqkv + 255) / 256, blk>>>((const float4*)W_qkv,  (float4*)p_wqkv_r, n4_wqkv);
        round_tf32_kernel<<<(n4_wout + 255) / 256, blk>>>((const float4*)W_out,  (float4*)p_wout_r, n4_wout);
    }

    gemm_mma_kernel<0><<<dim3((3 * D) / 128, (B * T) / 128), blk, GEMM_SMEM_BYTES>>>(
        p_in_r, p_wqkv_r, b_qkv, nullptr, D, 3 * D);

    attn_mma_kernel<<<dim3(T / AQT, H, B), blk, ATTN_SMEM_BYTES>>>(adj, mask);

    gemm_mma_kernel<1><<<dim3(D / 128, (B * T) / 128), blk, GEMM_SMEM_BYTES>>>(
        nullptr, p_wout_r, b_out, out, D, D);
}

// round 9
// speedup vs baseline: 3.3792x; 1.0250x over previous
#include <cuda_runtime.h>
#include <cstdint>

// ---------------- problem constants ----------------
constexpr int B  = 8;
constexpr int T  = 1024;
constexpr int D  = 1024;
constexpr int H  = 16;
constexpr int DH = 64;
constexpr float INV_SCALE = 0.125f;   // 1/sqrt(DH)
constexpr float QSCALE = 0.125f * 1.44269504088896340736f;  // log2(e)/8
constexpr float EPS = 1e-13f;

// ---------------- scratch (device globals: no allocation allowed) ----------------
__device__ float g_q[(size_t)B * H * T * DH];
__device__ float g_k[(size_t)B * H * T * DH];
__device__ float g_v[(size_t)B * H * T * DH];
__device__ float g_ctx[(size_t)B * T * D];
__device__ float g_in_r[(size_t)B * T * D];
__device__ float g_wqkv_r[(size_t)3 * D * D];
__device__ float g_wout_r[(size_t)D * D];

// ---------------- PTX helpers (base-arch only) ----------------
__device__ __forceinline__ uint32_t smem_u32(const void* p) {
    uint32_t a;
    asm("{ .reg .u64 t; cvta.to.shared.u64 t, %1; cvt.u32.u64 %0, t; }"
        : "=r"(a) : "l"(p));
    return a;
}

#define CP_ASYNC16(dst, src) \
    asm volatile("cp.async.cg.shared.global [%0], [%1], 16;" :: "r"(dst), "l"(src))
#define CP_ASYNC4(dst, src) \
    asm volatile("cp.async.ca.shared.global [%0], [%1], 4;" :: "r"(dst), "l"(src))
#define CP_COMMIT()  asm volatile("cp.async.commit_group;" ::: "memory")
#define CP_WAIT(n)   asm volatile("cp.async.wait_group %0;" :: "n"(n) : "memory")

#define LDMATRIX_X4(r0, r1, r2, r3, addr) \
    asm volatile("ldmatrix.sync.aligned.m8n8.x4.shared.b16 {%0,%1,%2,%3}, [%4];" \
        : "=r"(r0), "=r"(r1), "=r"(r2), "=r"(r3) : "r"(addr))

__device__ __forceinline__ uint32_t f2tf32(uint32_t x) {
    uint32_t d;
    asm("cvt.rna.tf32.f32 %0, %1;" : "=r"(d) : "r"(x));
    return d;
}
__device__ __forceinline__ float tf32r(float x) {
    return __uint_as_float(f2tf32(__float_as_uint(x)));
}
__device__ __forceinline__ float ex2(float x) {
    float r;
    asm("ex2.approx.f32 %0, %1;" : "=f"(r) : "f"(x));
    return r;
}

__device__ __forceinline__ void mma_tf32(float* c, const uint32_t* a,
                                         uint32_t b0, uint32_t b1) {
    asm volatile(
        "mma.sync.aligned.m16n8k8.row.col.f32.tf32.tf32.f32 "
        "{%0,%1,%2,%3}, {%4,%5,%6,%7}, {%8,%9}, {%0,%1,%2,%3};"
        : "+f"(c[0]), "+f"(c[1]), "+f"(c[2]), "+f"(c[3])
        : "r"(a[0]), "r"(a[1]), "r"(a[2]), "r"(a[3]), "r"(b0), "r"(b1));
}

// ============================================================================
// tf32 pre-round pass
// ============================================================================
__global__ void __launch_bounds__(256)
round_tf32_kernel(const float4* __restrict__ src, float4* __restrict__ dst, int n4)
{
    const int i = blockIdx.x * 256 + threadIdx.x;
    if (i < n4) {
        float4 v = src[i];
        v.x = tf32r(v.x); v.y = tf32r(v.y); v.z = tf32r(v.z); v.w = tf32r(v.w);
        dst[i] = v;
    }
}

// ============================================================================
// tf32 mma.sync GEMM, 3-stage cp.async pipeline + register fragment pipelining
// (unchanged from R8)
// ============================================================================
constexpr int GBK = 32;
constexpr int G_TILE  = 128 * 128;
constexpr int G_STAGE = 2 * G_TILE;
constexpr int GEMM_SMEM_BYTES = 3 * G_STAGE;    // 96 KB

__device__ __forceinline__ void load_chunk(uint32_t sA, uint32_t sB,
                                           const float* __restrict__ Ab,
                                           const float* __restrict__ Wb,
                                           int K, int k0) {
    const int tid = threadIdx.x;
#pragma unroll
    for (int it = 0; it < 4; it++) {
        const int idx = it * 256 + tid;
        const int r = idx >> 3;
        const int s = idx & 7;
        const uint32_t off = (uint32_t)r * 128u + (((uint32_t)s * 16u) ^ (((uint32_t)r & 7u) << 4));
        CP_ASYNC16(sA + off, Ab + (size_t)r * K + k0 + s * 4);
    }
#pragma unroll
    for (int it = 0; it < 4; it++) {
        const int idx = it * 256 + tid;
        const int r = idx >> 3;
        const int s = idx & 7;
        const uint32_t off = (uint32_t)r * 128u + (((uint32_t)s * 16u) ^ (((uint32_t)r & 7u) << 4));
        CP_ASYNC16(sB + off, Wb + (size_t)r * K + k0 + s * 4);
    }
}

template <int MODE>
__global__ void __launch_bounds__(256, 2)
gemm_mma_kernel(const float* __restrict__ A, const float* __restrict__ W,
                const float* __restrict__ bias, float* __restrict__ C,
                int K, int Ntot)
{
    extern __shared__ __align__(1024) char smem[];
    const uint32_t sbase = smem_u32(smem);
    const int tid  = threadIdx.x;
    const int wid  = tid >> 5;
    const int lane = tid & 31;

    const int m0 = blockIdx.y * 128;
    const int n0 = blockIdx.x * 128;

    const float* Asrc = (MODE == 1) ? (const float*)g_ctx : A;
    const float* Ab = Asrc + (size_t)m0 * K;
    const float* Wb = W    + (size_t)n0 * K;

    uint32_t sA[3], sB[3];
#pragma unroll
    for (int s = 0; s < 3; s++) {
        sA[s] = sbase + s * G_STAGE;
        sB[s] = sA[s] + G_TILE;
    }

    const int wm = (wid >> 2) * 64;
    const int wn = (wid & 3) * 32;

    const int arow       = wm + (lane & 15);
    const uint32_t aoff  = (uint32_t)arow * 128u;
    const uint32_t aswz  = ((uint32_t)arow & 7u) << 4;
    const uint32_t akhi  = (uint32_t)(lane & 16);
    const int brow       = wn + (lane & 7) + ((lane & 16) >> 1);
    const uint32_t boff  = (uint32_t)brow * 128u;
    const uint32_t bswz  = ((uint32_t)brow & 7u) << 4;
    const uint32_t bkhi  = (uint32_t)((lane & 8) << 1);

    float acc[4][4][4];
#pragma unroll
    for (int i = 0; i < 4; i++)
#pragma unroll
        for (int j = 0; j < 4; j++)
#pragma unroll
            for (int e = 0; e < 4; e++) acc[i][j][e] = 0.f;

    const int NC = K / GBK;

    load_chunk(sA[0], sB[0], Ab, Wb, K, 0);
    CP_COMMIT();
    load_chunk(sA[1], sB[1], Ab, Wb, K, GBK);
    CP_COMMIT();

    uint32_t afr[2][4][4], bfr[2][2][4];

    int st = 0;
    for (int i = 0; i < NC; i++) {
        CP_WAIT(1);
        __syncthreads();

        const int pst = (st + 2 >= 3) ? st + 2 - 3 : st + 2;
        if (i + 2 < NC)
            load_chunk(sA[pst], sB[pst], Ab, Wb, K, (i + 2) * GBK);
        CP_COMMIT();

        const uint32_t aB = sA[st];
        const uint32_t bB = sB[st];

#pragma unroll
        for (int tm = 0; tm < 4; tm++) {
            const uint32_t addr = aB + aoff + (uint32_t)tm * 2048u + (akhi ^ aswz);
            LDMATRIX_X4(afr[0][tm][0], afr[0][tm][1], afr[0][tm][2], afr[0][tm][3], addr);
        }
#pragma unroll
        for (int tp = 0; tp < 2; tp++) {
            const uint32_t addr = bB + boff + (uint32_t)tp * 2048u + (bkhi ^ bswz);
            LDMATRIX_X4(bfr[0][tp][0], bfr[0][tp][1], bfr[0][tp][2], bfr[0][tp][3], addr);
        }

#pragma unroll
        for (int ks = 0; ks < 4; ks++) {
            const int cb = ks & 1;
            if (ks < 3) {
                const int nb = cb ^ 1;
                const uint32_t kb = (uint32_t)(ks + 1) * 32u;
#pragma unroll
                for (int tm = 0; tm < 4; tm++) {
                    const uint32_t addr = aB + aoff + (uint32_t)tm * 2048u + ((kb + akhi) ^ aswz);
                    LDMATRIX_X4(afr[nb][tm][0], afr[nb][tm][1], afr[nb][tm][2], afr[nb][tm][3], addr);
                }
#pragma unroll
                for (int tp = 0; tp < 2; tp++) {
                    const uint32_t addr = bB + boff + (uint32_t)tp * 2048u + ((kb + bkhi) ^ bswz);
                    LDMATRIX_X4(bfr[nb][tp][0], bfr[nb][tp][1], bfr[nb][tp][2], bfr[nb][tp][3], addr);
                }
            }
#pragma unroll
            for (int tm = 0; tm < 4; tm++)
#pragma unroll
                for (int tn = 0; tn < 4; tn++)
                    mma_tf32(acc[tm][tn], afr[cb][tm],
                             bfr[cb][tn >> 1][(tn & 1) * 2 + 0],
                             bfr[cb][tn >> 1][(tn & 1) * 2 + 1]);
        }
        st = (st + 1 >= 3) ? 0 : st + 1;
    }

#pragma unroll
    for (int tm = 0; tm < 4; tm++) {
#pragma unroll
        for (int tn = 0; tn < 4; tn++) {
            const int col = n0 + wn + tn * 8 + (lane & 3) * 2;
            const float bx = bias[col], by = bias[col + 1];
#pragma unroll
            for (int half = 0; half < 2; half++) {
                const int row = m0 + wm + tm * 16 + (lane >> 2) + half * 8;
                float2 v;
                v.x = acc[tm][tn][half * 2 + 0] + bx;
                v.y = acc[tm][tn][half * 2 + 1] + by;
                if (MODE == 0) {
                    v.x = tf32r(v.x); v.y = tf32r(v.y);
                    const int sel = col >> 10;
                    float* dst = (sel == 0) ? g_q : (sel == 1) ? g_k : g_v;
                    const int bb = row >> 10;
                    const int t  = row & 1023;
                    const int hh = (col & 1023) >> 6;
                    const int d  = col & 63;
                    *(float2*)&dst[((size_t)(bb * H + hh) * T + t) * DH + d] = v;
                } else {
                    *(float2*)&C[(size_t)row * Ntot + col] = v;
                }
            }
        }
    }
}

// ============================================================================
// Fused flash attention, tf32 mma.sync, max-free softmax (exp2 form).
//   adj: direct LDG into registers (no SMEM round-trip).
//   mask: loaded once per tile into registers.
//   Q pre-scaled by log2(e)/8 and re-rounded to tf32.
// ============================================================================
constexpr int AQT = 128;
constexpr int AKT = 64;
constexpr int ASS = 68;
constexpr int OFF_Q  = 0;                  // [128][68]
constexpr int OFF_K0 = OFF_Q  + AQT * ASS; // [64][68]
constexpr int OFF_K1 = OFF_K0 + AKT * ASS;
constexpr int OFF_V0 = OFF_K1 + AKT * ASS; // [64][68] transposed chunk-XOR
constexpr int OFF_V1 = OFF_V0 + AKT * ASS;
constexpr int OFF_P  = OFF_V1 + AKT * ASS; // [128][68]
constexpr int OFF_M0 = OFF_P  + AQT * ASS; // [64]
constexpr int OFF_M1 = OFF_M0 + AKT;
constexpr int ATTN_SMEM_BYTES = (OFF_M1 + AKT) * 4;   // ~139.8 KB

__device__ __forceinline__ void attn_load_tile(
    uint32_t sKb, uint32_t sVb, uint32_t sMb,
    const float* __restrict__ kbase, const float* __restrict__ vbase,
    const float* __restrict__ mrow, int kk0, int tid)
{
#pragma unroll
    for (int it = 0; it < 4; it++) {
        const int idx = it * 256 + tid;
        const int r = idx >> 4, s = idx & 15;
        CP_ASYNC16(sKb + (uint32_t)r * 272u + (uint32_t)s * 16u,
                   kbase + (size_t)(kk0 + r) * DH + s * 4);
    }
#pragma unroll
    for (int it = 0; it < 16; it++) {
        const int idx = it * 256 + tid;
        const int c = idx >> 6;
        const int d = idx & 63;
        const uint32_t byte = (uint32_t)d * 272u +
                              (((uint32_t)c * 4u) ^ ((((uint32_t)d >> 3) & 3u) << 4));
        CP_ASYNC4(sVb + byte, vbase + (size_t)(kk0 + c) * DH + d);
    }
    if (tid < 16)
        CP_ASYNC16(sMb + (uint32_t)tid * 16u, mrow + kk0 + tid * 4);
}

__global__ void __launch_bounds__(256, 1)
attn_mma_kernel(const float* __restrict__ adj, const float* __restrict__ mask)
{
    extern __shared__ __align__(16) float sh[];

    const int b   = blockIdx.z;
    const int h   = blockIdx.y;
    const int q0g = blockIdx.x * AQT;
    const int tid = threadIdx.x;
    const int wid = tid >> 5;
    const int lane = tid & 31;
    const int q0  = wid * 16;

    const float* qptr  = g_q + ((size_t)(b * H + h) * T + q0g) * DH;
    const float* kbase = g_k + (size_t)(b * H + h) * T * DH;
    const float* vbase = g_v + (size_t)(b * H + h) * T * DH;
    const float* aptr  = adj + ((size_t)b * T + q0g) * T;
    const float* mrow  = mask + (size_t)b * T;

    const uint32_t sbase = smem_u32(sh);
    const uint32_t sQ = sbase + OFF_Q * 4;
    const uint32_t sK[2] = { sbase + OFF_K0 * 4, sbase + OFF_K1 * 4 };
    const uint32_t sV[2] = { sbase + OFF_V0 * 4, sbase + OFF_V1 * 4 };
    const uint32_t sP = sbase + OFF_P * 4;
    float* Ps = sh + OFF_P;

    // ---- load Q once: scale by log2(e)/8, re-round to tf32 ----
#pragma unroll
    for (int it = 0; it < 8; it++) {
        const int idx = it * 256 + tid;
        const int r = idx >> 4, s = idx & 15;
        float4 v = *(const float4*)(qptr + (size_t)r * DH + s * 4);
        v.x = tf32r(v.x * QSCALE); v.y = tf32r(v.y * QSCALE);
        v.z = tf32r(v.z * QSCALE); v.w = tf32r(v.w * QSCALE);
        *(float4*)(sh + OFF_Q + r * ASS + s * 4) = v;
    }

    // prefetch tile 0 while Q stores drain
    attn_load_tile(sK[0], sV[0], sbase + OFF_M0 * 4, kbase, vbase, mrow, 0, tid);
    CP_COMMIT();

    const uint32_t a_row_off = (uint32_t)(q0 + (lane & 15)) * 272u;
    const uint32_t a_khi     = (uint32_t)(lane & 16);
    const int      b_rl      = (lane & 7) + ((lane & 16) >> 1);
    const uint32_t b_khi     = (uint32_t)((lane & 8) << 1);

    // softmax-phase row/col for this lane (C-fragment layout)
    const int rq_lo = q0 + (lane >> 2);          // hh=0 row (block-local)
    const int ccol0 = (lane & 3) * 2;            // col offset within an 8-wide tile

    __syncthreads();   // Q stores visible to all warps

    // ---- hoist Q fragments to registers (loop-invariant) ----
    uint32_t qfr[8][4];
#pragma unroll
    for (int ks = 0; ks < 8; ks++) {
        LDMATRIX_X4(qfr[ks][0], qfr[ks][1], qfr[ks][2], qfr[ks][3],
                    sQ + a_row_off + (uint32_t)ks * 32u + a_khi);
    }

    float oacc[8][4];
#pragma unroll
    for (int tn = 0; tn < 8; tn++)
#pragma unroll
        for (int e = 0; e < 4; e++) oacc[tn][e] = 0.f;
    float l1[2] = { 0.f, 0.f };
    float l2[2] = { 0.f, 0.f };

    constexpr int NT = T / AKT;
    uint32_t bfr[2][4][4];

    for (int kt = 0; kt < NT; kt++) {
        const int cur = kt & 1;
        const int kk0 = kt * AKT;

        CP_WAIT(0);
        __syncthreads();

        // ---- adj -> registers, issued early (consumed after S-mma) ----
        float2 areg[2][8];
#pragma unroll
        for (int hh = 0; hh < 2; hh++) {
            const float* arow = aptr + (size_t)(rq_lo + 8 * hh) * T + kk0 + ccol0;
#pragma unroll
            for (int tn = 0; tn < 8; tn++)
                areg[hh][tn] = *(const float2*)(arow + tn * 8);
        }

        if (kt + 1 < NT) {
            attn_load_tile(sK[1 - cur], sV[1 - cur],
                           sbase + (cur ? OFF_M0 : OFF_M1) * 4,
                           kbase, vbase, mrow, (kt + 1) * AKT, tid);
        }
        CP_COMMIT();

        const uint32_t sKb = sK[cur];
        const uint32_t sVb = sV[cur];
        const float* Ms = sh + (cur ? OFF_M1 : OFF_M0);

        // ---- mask -> registers once (shared by both hh halves) ----
        float2 mreg[8];
#pragma unroll
        for (int tn = 0; tn < 8; tn++)
            mreg[tn] = *(const float2*)&Ms[tn * 8 + ccol0];

        // ---- S = Q @ K^T, K fragments register-pipelined ----
        float sacc[8][4];
#pragma unroll
        for (int tn = 0; tn < 8; tn++)
#pragma unroll
            for (int e = 0; e < 4; e++) sacc[tn][e] = 0.f;

#pragma unroll
        for (int tp = 0; tp < 4; tp++) {
            const uint32_t addr = sKb + (uint32_t)(tp * 16 + b_rl) * 272u + b_khi;
            LDMATRIX_X4(bfr[0][tp][0], bfr[0][tp][1], bfr[0][tp][2], bfr[0][tp][3], addr);
        }
#pragma unroll
        for (int ks = 0; ks < 8; ks++) {
            const int cb = ks & 1;
            if (ks < 7) {
                const int nb = cb ^ 1;
                const uint32_t kb = (uint32_t)(ks + 1) * 32u;
#pragma unroll
                for (int tp = 0; tp < 4; tp++) {
                    const uint32_t addr = sKb + (uint32_t)(tp * 16 + b_rl) * 272u + kb + b_khi;
                    LDMATRIX_X4(bfr[nb][tp][0], bfr[nb][tp][1], bfr[nb][tp][2], bfr[nb][tp][3], addr);
                }
            }
#pragma unroll
            for (int tn = 0; tn < 8; tn++)
                mma_tf32(sacc[tn], qfr[ks],
                         bfr[cb][tn >> 1][(tn & 1) * 2 + 0],
                         bfr[cb][tn >> 1][(tn & 1) * 2 + 1]);
        }

        // ---- max-free softmax: p = exp2(s*adj*m) (log2e folded into Q) ----
#pragma unroll
        for (int hh = 0; hh < 2; hh++) {
            const int rq = rq_lo + 8 * hh;
            float s1s = 0.f, s2s = 0.f;
#pragma unroll
            for (int tn = 0; tn < 8; tn++) {
                const float p0 = ex2(sacc[tn][2 * hh + 0] * areg[hh][tn].x * mreg[tn].x);
                const float p1 = ex2(sacc[tn][2 * hh + 1] * areg[hh][tn].y * mreg[tn].y);
                const float pm0 = p0 * mreg[tn].x;
                const float pm1 = p1 * mreg[tn].y;
                s2s += p0 + p1;
                s1s += pm0 + pm1;
                float2 pw;
                pw.x = tf32r(pm0);
                pw.y = tf32r(pm1);
                *(float2*)&Ps[rq * ASS + tn * 8 + ccol0] = pw;
            }
            s1s += __shfl_xor_sync(0xffffffffu, s1s, 1);
            s1s += __shfl_xor_sync(0xffffffffu, s1s, 2);
            s2s += __shfl_xor_sync(0xffffffffu, s2s, 1);
            s2s += __shfl_xor_sync(0xffffffffu, s2s, 2);
            l1[hh] += s1s; l2[hh] += s2s;
        }
        __syncwarp();

        // ---- O += P @ V, V fragments register-pipelined ----
#pragma unroll
        for (int tp = 0; tp < 4; tp++) {
            const uint32_t row = (uint32_t)(tp * 16 + b_rl);
            const uint32_t byteoff = b_khi ^ (((row >> 3) & 3u) << 4);
            LDMATRIX_X4(bfr[0][tp][0], bfr[0][tp][1], bfr[0][tp][2], bfr[0][tp][3],
                        sVb + row * 272u + byteoff);
        }
#pragma unroll
        for (int cs = 0; cs < 8; cs++) {
            const int cb = cs & 1;
            const uint32_t kb = (uint32_t)cs * 32u;
            uint32_t afr[4];
            LDMATRIX_X4(afr[0], afr[1], afr[2], afr[3], sP + a_row_off + kb + a_khi);
            if (cs < 7) {
                const int nb = cb ^ 1;
                const uint32_t kb2 = (uint32_t)(cs + 1) * 32u;
#pragma unroll
                for (int tp = 0; tp < 4; tp++) {
                    const uint32_t row = (uint32_t)(tp * 16 + b_rl);
                    const uint32_t byteoff = (kb2 + b_khi) ^ (((row >> 3) & 3u) << 4);
                    LDMATRIX_X4(bfr[nb][tp][0], bfr[nb][tp][1], bfr[nb][tp][2], bfr[nb][tp][3],
                                sVb + row * 272u + byteoff);
                }
            }
#pragma unroll
            for (int tn = 0; tn < 8; tn++)
                mma_tf32(oacc[tn], afr,
                         bfr[cb][tn >> 1][(tn & 1) * 2 + 0],
                         bfr[cb][tn >> 1][(tn & 1) * 2 + 1]);
        }
    }

    // ---- normalize, tf32-round, write ctx ----
#pragma unroll
    for (int hh = 0; hh < 2; hh++) {
        const float inv = 1.0f / (l1[hh] + EPS * l2[hh]);
        const int gq = q0g + rq_lo + 8 * hh;
#pragma unroll
        for (int tn = 0; tn < 8; tn++) {
            const int d = tn * 8 + ccol0;
            float2 o;
            o.x = tf32r(oacc[tn][2 * hh + 0] * inv);
            o.y = tf32r(oacc[tn][2 * hh + 1] * inv);
            *(float2*)&g_ctx[(size_t)(b * T + gq) * D + h * DH + d] = o;
        }
    }
}

// ============================================================================
// launch
// ============================================================================
extern "C" void kernel_launch(void* const* d_in, const int* in_sizes, int n_in,
                              void* d_out, int out_size)
{
    (void)in_sizes; (void)n_in; (void)out_size;
    const float* inputs = (const float*)d_in[0];
    const float* mask   = (const float*)d_in[1];
    const float* adj    = (const float*)d_in[2];
    const float* W_qkv  = (const float*)d_in[3];
    const float* b_qkv  = (const float*)d_in[4];
    const float* W_out  = (const float*)d_in[5];
    const float* b_out  = (const float*)d_in[6];
    float* out = (float*)d_out;

    cudaFuncSetAttribute(gemm_mma_kernel<0>,
                         cudaFuncAttributeMaxDynamicSharedMemorySize,
                         GEMM_SMEM_BYTES);
    cudaFuncSetAttribute(gemm_mma_kernel<1>,
                         cudaFuncAttributeMaxDynamicSharedMemorySize,
                         GEMM_SMEM_BYTES);
    cudaFuncSetAttribute(attn_mma_kernel,
                         cudaFuncAttributeMaxDynamicSharedMemorySize,
                         ATTN_SMEM_BYTES);

    float *p_in_r, *p_wqkv_r, *p_wout_r;
    cudaGetSymbolAddress((void**)&p_in_r,   g_in_r);
    cudaGetSymbolAddress((void**)&p_wqkv_r, g_wqkv_r);
    cudaGetSymbolAddress((void**)&p_wout_r, g_wout_r);

    dim3 blk(256);

    {
        const int n4_in   = (B * T * D) / 4;
        const int n4_wqkv = (3 * D * D) / 4;
        const int n4_wout = (D * D) / 4;
        round_tf32_kernel<<<(n4_in   + 255) / 256, blk>>>((const float4*)inputs, (float4*)p_in_r,   n4_in);
        round_tf32_kernel<<<(n4_wqkv + 255) / 256, blk>>>((const float4*)W_qkv,  (float4*)p_wqkv_r, n4_wqkv);
        round_tf32_kernel<<<(n4_wout + 255) / 256, blk>>>((const float4*)W_out,  (float4*)p_wout_r, n4_wout);
    }

    gemm_mma_kernel<0><<<dim3((3 * D) / 128, (B * T) / 128), blk, GEMM_SMEM_BYTES>>>(
        p_in_r, p_wqkv_r, b_qkv, nullptr, D, 3 * D);

    attn_mma_kernel<<<dim3(T / AQT, H, B), blk, ATTN_SMEM_BYTES>>>(adj, mask);

    gemm_mma_kernel<1><<<dim3(D / 128, (B * T) / 128), blk, GEMM_SMEM_BYTES>>>(
        nullptr, p_wout_r, b_out, out, D, D);
}